// round 5
// baseline (speedup 1.0000x reference)
#include <cuda_runtime.h>
#include <cstdint>

// ---------------------------------------------------------------------------
// Problem constants (fixed shapes from reference setup_inputs)
// ---------------------------------------------------------------------------
#define BB   4
#define TT   4096
#define NN   512
#define DD   1024
#define LL   768
#define HH   8
#define HD   128

// ---------------------------------------------------------------------------
// Scratch (single __device__ array; no allocations anywhere)
// ---------------------------------------------------------------------------
#define OFF_XN  0LL                                  // [B*T, D]      16777216
#define OFF_CN  (OFF_XN + 16777216LL)                // [B*N, L]       1572864
#define OFF_Q   (OFF_CN + 1572864LL)                 // [B*T, D]      16777216
#define OFF_K   (OFF_Q  + 16777216LL)                // [B*N, D]       2097152
#define OFF_V   (OFF_K  + 2097152LL)                 // [B*N, D]       2097152
#define OFF_KM  (OFF_V  + 2097152LL)                 // [B, D]            4096
#define OFF_KS  (OFF_KM + 4096LL)                    // [B, D]            4096
#define OFF_CP  (OFF_KS + 4096LL)                    // [4, B*H,128,128] 2097152
#define OFF_CTX (OFF_CP + 2097152LL)                 // [B*H,128,128]   524288
#define OFF_WQR (OFF_CTX + 524288LL)                 // [1024,1024]    1048576
#define OFF_WKR (OFF_WQR + 1048576LL)                // [768,1024]      786432
#define OFF_WVR (OFF_WKR + 786432LL)                 // [768,1024]      786432
#define SCRATCH_TOTAL (OFF_WVR + 786432LL)

__device__ __align__(256) float g_buf[SCRATCH_TOTAL];

// ---------------------------------------------------------------------------
// Helpers
// ---------------------------------------------------------------------------
__device__ __forceinline__ float f2tf32f(float x) {
    uint32_t u;
    asm("cvt.rna.tf32.f32 %0, %1;" : "=r"(u) : "f"(x));
    return __uint_as_float(u);
}

__device__ __forceinline__ void mma_tf32(float* c, const uint32_t* a, const uint32_t* b) {
    asm volatile(
        "mma.sync.aligned.m16n8k8.row.col.f32.tf32.tf32.f32 "
        "{%0,%1,%2,%3}, {%4,%5,%6,%7}, {%8,%9}, {%0,%1,%2,%3};\n"
        : "+f"(c[0]), "+f"(c[1]), "+f"(c[2]), "+f"(c[3])
        : "r"(a[0]), "r"(a[1]), "r"(a[2]), "r"(a[3]),
          "r"(b[0]), "r"(b[1]));
}

__device__ __forceinline__ void ldsm4(uint32_t& r0, uint32_t& r1, uint32_t& r2,
                                      uint32_t& r3, uint32_t addr) {
    asm volatile("ldmatrix.sync.aligned.m8n8.x4.shared.b16 {%0,%1,%2,%3}, [%4];\n"
                 : "=r"(r0), "=r"(r1), "=r"(r2), "=r"(r3) : "r"(addr));
}

__device__ __forceinline__ void cp16(void* s, const void* g) {
    uint32_t sa = (uint32_t)__cvta_generic_to_shared(s);
    asm volatile("cp.async.cg.shared.global [%0], [%1], 16;\n" :: "r"(sa), "l"(g));
}

// ---------------------------------------------------------------------------
// Pre-round weights to tf32 (single pass, float4)
// layout: [Wq 1048576 | Wk 786432 | Wv 786432]
// ---------------------------------------------------------------------------
__global__ void round_weights(const float* __restrict__ wq, const float* __restrict__ wk,
                              const float* __restrict__ wv, float* __restrict__ out) {
    const size_t fi = ((size_t)blockIdx.x * 256 + threadIdx.x) * 4;
    const float* src;
    size_t off;
    if (fi < 1048576) { src = wq; off = fi; }
    else if (fi < 1048576 + 786432) { src = wk; off = fi - 1048576; }
    else { src = wv; off = fi - (1048576 + 786432); }
    float4 v = *(const float4*)(src + off);
    v.x = f2tf32f(v.x); v.y = f2tf32f(v.y);
    v.z = f2tf32f(v.z); v.w = f2tf32f(v.w);
    *(float4*)(out + fi) = v;
}

// ---------------------------------------------------------------------------
// LayerNorm: one block per row; output pre-rounded to tf32 (GEMM operand)
// ---------------------------------------------------------------------------
template <int DIM>
__global__ void ln_kernel(const float* __restrict__ x, const float* __restrict__ g,
                          const float* __restrict__ bta, float* __restrict__ out) {
    constexpr int PER = DIM / 256;
    const size_t row = blockIdx.x;
    const float* xr = x + row * DIM;
    float v[PER];
    float s = 0.f, sq = 0.f;
#pragma unroll
    for (int i = 0; i < PER; i++) {
        v[i] = xr[threadIdx.x + 256 * i];
        s += v[i];
        sq += v[i] * v[i];
    }
#pragma unroll
    for (int o = 16; o; o >>= 1) {
        s += __shfl_xor_sync(0xffffffffu, s, o);
        sq += __shfl_xor_sync(0xffffffffu, sq, o);
    }
    __shared__ float sm[8], sv[8];
    int w = threadIdx.x >> 5;
    if ((threadIdx.x & 31) == 0) { sm[w] = s; sv[w] = sq; }
    __syncthreads();
    if (threadIdx.x < 32) {
        s = (threadIdx.x < 8) ? sm[threadIdx.x] : 0.f;
        sq = (threadIdx.x < 8) ? sv[threadIdx.x] : 0.f;
#pragma unroll
        for (int o = 4; o; o >>= 1) {
            s += __shfl_xor_sync(0xffffffffu, s, o);
            sq += __shfl_xor_sync(0xffffffffu, sq, o);
        }
        if (threadIdx.x == 0) { sm[0] = s; sv[0] = sq; }
    }
    __syncthreads();
    const float mean = sm[0] * (1.f / DIM);
    const float var = sv[0] * (1.f / DIM) - mean * mean;
    const float rstd = rsqrtf(var + 1e-5f);
    float* orow = out + row * DIM;
#pragma unroll
    for (int i = 0; i < PER; i++) {
        int c = threadIdx.x + 256 * i;
        orow[c] = f2tf32f((v[i] - mean) * rstd * g[c] + bta[c]);
    }
}

// ---------------------------------------------------------------------------
// tf32 tensor-core GEMM: C[M,N] = A[M,K] @ W[K,N] (+bias)
// Inputs MUST be pre-rounded to tf32. 128x128 tile, BK=16, cp.async 4-stage.
// A fragments via ldmatrix.x4; B via conflict-free scalar LDS; zero in-loop cvt.
// FUSE_SM: row softmax over the 128-col tile (== one head) in epilogue,
//          output rounded to tf32 (feeds next GEMM).
// Dual mode (Bm2 != null): grid.x split between {Bm,bias,C} and {Bm2,bias2,C2}.
// ---------------------------------------------------------------------------
#define STAGES 4
#define AS_STRIDE 20
#define BS_STRIDE 136
#define A_ST_FLOATS (128 * AS_STRIDE)
#define B_ST_FLOATS (16 * BS_STRIDE)
#define SMEM_FLOATS (STAGES * (A_ST_FLOATS + B_ST_FLOATS))
#define SMEM_BYTES (SMEM_FLOATS * 4)

template <bool FUSE_SM>
__global__ void __launch_bounds__(256, 2)
gemm_tf32(const float* __restrict__ A, const float* __restrict__ Bm,
          const float* __restrict__ bias, float* __restrict__ C,
          const float* __restrict__ Bm2, const float* __restrict__ bias2,
          float* __restrict__ C2,
          int K, int lda, int ldb, int ldc,
          int Hdiv, long long sA0, long long sA1, long long sB,
          long long sC0, long long sC1) {
    extern __shared__ float smem[];
    float* Asm = smem;                         // [STAGES][128][20]
    float* Bsm = smem + STAGES * A_ST_FLOATS;  // [STAGES][16][136]

    int tN;
    if (Bm2 != nullptr) {
        const int half = gridDim.x >> 1;
        if (blockIdx.x >= half) {
            Bm = Bm2; bias = bias2; C = C2;
            tN = (blockIdx.x - half) * 128;
        } else {
            tN = blockIdx.x * 128;
        }
    } else {
        const int z = blockIdx.z;
        const int zb = z / Hdiv, zh = z - zb * Hdiv;
        A += zb * sA0 + zh * sA1;
        Bm += (long long)z * sB;
        C += zb * sC0 + zh * sC1;
        tN = blockIdx.x * 128;
    }
    const int tM = blockIdx.y * 128;
    const int tid = threadIdx.x;
    const int lane = tid & 31, warp = tid >> 5;
    const int m_base = (warp & 1) * 64;
    const int n_base = (warp >> 1) * 32;

    const float* Ag = A + (size_t)tM * lda;
    const float* Bg = Bm + tN;
    const int nk = K >> 4;

    // producer indexing (each thread: 2 A + 2 B 16B chunks per stage)
    const int ar0 = tid >> 2;
    const int ac0 = (tid & 3) * 4;
    const int br0 = tid >> 5;
    const int bc0 = (tid & 31) * 4;

    auto issue = [&](int kt) {
        const int st = kt & (STAGES - 1);
        float* Al = Asm + st * A_ST_FLOATS;
        float* Bl = Bsm + st * B_ST_FLOATS;
        const int k0 = kt << 4;
        cp16(Al + ar0 * AS_STRIDE + ac0, Ag + (size_t)ar0 * lda + k0 + ac0);
        cp16(Al + (ar0 + 64) * AS_STRIDE + ac0, Ag + (size_t)(ar0 + 64) * lda + k0 + ac0);
        cp16(Bl + br0 * BS_STRIDE + bc0, Bg + (size_t)(k0 + br0) * ldb + bc0);
        cp16(Bl + (br0 + 8) * BS_STRIDE + bc0, Bg + (size_t)(k0 + br0 + 8) * ldb + bc0);
    };

    // ldmatrix per-lane constant offset:
    // mat 0: rows m..m+7  k0-3 | mat 1: rows +8 k0-3 | mat 2: rows m..m+7 k4-7 | mat 3: rows +8 k4-7
    const int mat = lane >> 3, mj = lane & 7;
    const int lrow = ((mat & 1) << 3) + mj;
    const int lkof = (mat >> 1) << 2;
    const uint32_t asm_u32 = (uint32_t)__cvta_generic_to_shared(Asm);
    const uint32_t a_lane_b = ((m_base + lrow) * AS_STRIDE + lkof) * 4u;

    float acc[4][4][4];
#pragma unroll
    for (int i = 0; i < 4; i++)
#pragma unroll
        for (int j = 0; j < 4; j++)
#pragma unroll
            for (int r = 0; r < 4; r++) acc[i][j][r] = 0.f;

#pragma unroll
    for (int s = 0; s < STAGES - 1; s++) {
        issue(s);   // nk >= 8 for all launches in this problem
        asm volatile("cp.async.commit_group;\n");
    }

    for (int kt = 0; kt < nk; kt++) {
        if (kt + STAGES - 1 < nk) issue(kt + STAGES - 1);
        asm volatile("cp.async.commit_group;\n");
        asm volatile("cp.async.wait_group %0;\n" :: "n"(STAGES - 1));
        __syncthreads();

        const int st = kt & (STAGES - 1);
        const uint32_t a_st = asm_u32 + (uint32_t)(st * A_ST_FLOATS * 4) + a_lane_b;
        const uint32_t* Bl = (const uint32_t*)(Bsm + st * B_ST_FLOATS);
#pragma unroll
        for (int kk = 0; kk < 2; kk++) {
            uint32_t af[4][4];
#pragma unroll
            for (int im = 0; im < 4; im++)
                ldsm4(af[im][0], af[im][1], af[im][2], af[im][3],
                      a_st + (uint32_t)((im * 16 * AS_STRIDE + kk * 8) * 4));
            uint32_t bf[4][2];
#pragma unroll
            for (int in = 0; in < 4; in++) {
                const int cc = n_base + in * 8 + (lane >> 2);
                const int kr = kk * 8 + (lane & 3);
                bf[in][0] = Bl[kr * BS_STRIDE + cc];
                bf[in][1] = Bl[(kr + 4) * BS_STRIDE + cc];
            }
#pragma unroll
            for (int im = 0; im < 4; im++)
#pragma unroll
                for (int in = 0; in < 4; in++)
                    mma_tf32(acc[im][in], af[im], bf[in]);
        }
        __syncthreads();
    }

    // -------- epilogue --------
    float b0[4], b1[4];
#pragma unroll
    for (int in = 0; in < 4; in++) {
        if (bias != nullptr) {
            const int c = tN + n_base + in * 8 + 2 * (lane & 3);
            b0[in] = __ldg(bias + c);
            b1[in] = __ldg(bias + c + 1);
        } else { b0[in] = 0.f; b1[in] = 0.f; }
    }
#pragma unroll
    for (int im = 0; im < 4; im++)
#pragma unroll
        for (int in = 0; in < 4; in++) {
            acc[im][in][0] += b0[in];
            acc[im][in][1] += b1[in];
            acc[im][in][2] += b0[in];
            acc[im][in][3] += b1[in];
        }

    if (FUSE_SM) {
        float* red = smem;
        float* red2 = smem + 512;
        const int wn = warp >> 1;

        float m0[4], m1[4];
#pragma unroll
        for (int im = 0; im < 4; im++) {
            float a = -1e30f, b = -1e30f;
#pragma unroll
            for (int in = 0; in < 4; in++) {
                a = fmaxf(a, fmaxf(acc[im][in][0], acc[im][in][1]));
                b = fmaxf(b, fmaxf(acc[im][in][2], acc[im][in][3]));
            }
            a = fmaxf(a, __shfl_xor_sync(0xffffffffu, a, 1));
            a = fmaxf(a, __shfl_xor_sync(0xffffffffu, a, 2));
            b = fmaxf(b, __shfl_xor_sync(0xffffffffu, b, 1));
            b = fmaxf(b, __shfl_xor_sync(0xffffffffu, b, 2));
            m0[im] = a; m1[im] = b;
        }
        if ((lane & 3) == 0) {
#pragma unroll
            for (int im = 0; im < 4; im++) {
                const int r = m_base + im * 16 + (lane >> 2);
                red[r * 4 + wn] = m0[im];
                red[(r + 8) * 4 + wn] = m1[im];
            }
        }
        __syncthreads();
        float M0[4], M1[4];
#pragma unroll
        for (int im = 0; im < 4; im++) {
            const int r = m_base + im * 16 + (lane >> 2);
            M0[im] = fmaxf(fmaxf(red[r * 4], red[r * 4 + 1]),
                           fmaxf(red[r * 4 + 2], red[r * 4 + 3]));
            M1[im] = fmaxf(fmaxf(red[(r + 8) * 4], red[(r + 8) * 4 + 1]),
                           fmaxf(red[(r + 8) * 4 + 2], red[(r + 8) * 4 + 3]));
        }
        float s0[4], s1[4];
#pragma unroll
        for (int im = 0; im < 4; im++) {
            float sa = 0.f, sb = 0.f;
#pragma unroll
            for (int in = 0; in < 4; in++) {
                acc[im][in][0] = __expf(acc[im][in][0] - M0[im]);
                acc[im][in][1] = __expf(acc[im][in][1] - M0[im]);
                acc[im][in][2] = __expf(acc[im][in][2] - M1[im]);
                acc[im][in][3] = __expf(acc[im][in][3] - M1[im]);
                sa += acc[im][in][0] + acc[im][in][1];
                sb += acc[im][in][2] + acc[im][in][3];
            }
            sa += __shfl_xor_sync(0xffffffffu, sa, 1);
            sa += __shfl_xor_sync(0xffffffffu, sa, 2);
            sb += __shfl_xor_sync(0xffffffffu, sb, 1);
            sb += __shfl_xor_sync(0xffffffffu, sb, 2);
            s0[im] = sa; s1[im] = sb;
        }
        if ((lane & 3) == 0) {
#pragma unroll
            for (int im = 0; im < 4; im++) {
                const int r = m_base + im * 16 + (lane >> 2);
                red2[r * 4 + wn] = s0[im];
                red2[(r + 8) * 4 + wn] = s1[im];
            }
        }
        __syncthreads();
#pragma unroll
        for (int im = 0; im < 4; im++) {
            const int r = m_base + im * 16 + (lane >> 2);
            const float inv0 = 1.f / (red2[r * 4] + red2[r * 4 + 1] +
                                      red2[r * 4 + 2] + red2[r * 4 + 3]);
            const float inv1 = 1.f / (red2[(r + 8) * 4] + red2[(r + 8) * 4 + 1] +
                                      red2[(r + 8) * 4 + 2] + red2[(r + 8) * 4 + 3]);
            const int r0 = tM + r;
#pragma unroll
            for (int in = 0; in < 4; in++) {
                const int c = tN + n_base + in * 8 + 2 * (lane & 3);
                *(float2*)(C + (size_t)r0 * ldc + c) =
                    make_float2(f2tf32f(acc[im][in][0] * inv0),
                                f2tf32f(acc[im][in][1] * inv0));
                *(float2*)(C + (size_t)(r0 + 8) * ldc + c) =
                    make_float2(f2tf32f(acc[im][in][2] * inv1),
                                f2tf32f(acc[im][in][3] * inv1));
            }
        }
    } else {
#pragma unroll
        for (int im = 0; im < 4; im++) {
            const int r0 = tM + m_base + im * 16 + (lane >> 2);
#pragma unroll
            for (int in = 0; in < 4; in++) {
                const int c = tN + n_base + in * 8 + 2 * (lane & 3);
                *(float2*)(C + (size_t)r0 * ldc + c) =
                    make_float2(acc[im][in][0], acc[im][in][1]);
                *(float2*)(C + (size_t)(r0 + 8) * ldc + c) =
                    make_float2(acc[im][in][2], acc[im][in][3]);
            }
        }
    }
}

// ---------------------------------------------------------------------------
// k column softmax stats (max, sumexp over N=512 per (b, d) column)
// ---------------------------------------------------------------------------
__global__ void kcol_stats(const float* __restrict__ k, float* __restrict__ om,
                           float* __restrict__ os) {
    const int b = blockIdx.x >> 5;
    const int cg = blockIdx.x & 31;
    const int cl = threadIdx.x & 31;
    const int seg = threadIdx.x >> 5;
    const int col = cg * 32 + cl;
    const float* p = k + (size_t)b * NN * DD + col;

    float m = -1e30f;
#pragma unroll 4
    for (int i = 0; i < 128; i++) m = fmaxf(m, p[(size_t)(seg * 128 + i) * DD]);

    __shared__ float smx[4][32], ssm[4][32], gmx[32];
    smx[seg][cl] = m;
    __syncthreads();
    if (seg == 0) {
        float M = fmaxf(fmaxf(smx[0][cl], smx[1][cl]), fmaxf(smx[2][cl], smx[3][cl]));
        gmx[cl] = M;
    }
    __syncthreads();
    const float M = gmx[cl];
    float s = 0.f;
#pragma unroll 4
    for (int i = 0; i < 128; i++) s += __expf(p[(size_t)(seg * 128 + i) * DD] - M);
    ssm[seg][cl] = s;
    __syncthreads();
    if (seg == 0) {
        float S = ssm[0][cl] + ssm[1][cl] + ssm[2][cl] + ssm[3][cl];
        om[b * DD + col] = M;
        os[b * DD + col] = S;
    }
}

// ---------------------------------------------------------------------------
// context partials: ctx[b,h,dk,dv] = (1/s_dk) * sum_n exp(k-m_dk) * v
// ---------------------------------------------------------------------------
__global__ void __launch_bounds__(256)
context_part(const float* __restrict__ k, const float* __restrict__ v,
             const float* __restrict__ km, const float* __restrict__ ks,
             float* __restrict__ cp) {
    const int bh = blockIdx.x;
    const int b = bh >> 3, h = bh & 7;
    const int split = blockIdx.y;
    __shared__ float Ks[32][132], Vs[32][132];

    const float* kb = k + (size_t)b * NN * DD + h * HD;
    const float* vb = v + (size_t)b * NN * DD + h * HD;
    const float* kmb = km + b * DD + h * HD;
    const float* ksb = ks + b * DD + h * HD;

    float acc[8][8];
#pragma unroll
    for (int i = 0; i < 8; i++)
#pragma unroll
        for (int j = 0; j < 8; j++) acc[i][j] = 0.f;

    const int tx = threadIdx.x & 15, ty = threadIdx.x >> 4;

    for (int c = 0; c < 4; c++) {
        const int n0 = split * 128 + c * 32;
        for (int t = threadIdx.x; t < 32 * 128; t += 256) {
            int nn = t >> 7, dd = t & 127;
            Ks[nn][dd] = __expf(kb[(size_t)(n0 + nn) * DD + dd] - kmb[dd]);
            Vs[nn][dd] = vb[(size_t)(n0 + nn) * DD + dd];
        }
        __syncthreads();
#pragma unroll 8
        for (int nn = 0; nn < 32; nn++) {
            float kr[8], vr[8];
#pragma unroll
            for (int i = 0; i < 8; i++) kr[i] = Ks[nn][ty * 8 + i];
#pragma unroll
            for (int j = 0; j < 8; j++) vr[j] = Vs[nn][tx * 8 + j];
#pragma unroll
            for (int i = 0; i < 8; i++)
#pragma unroll
                for (int j = 0; j < 8; j++) acc[i][j] += kr[i] * vr[j];
        }
        __syncthreads();
    }

    float* out = cp + ((size_t)split * 32 + bh) * (HD * HD);
#pragma unroll
    for (int i = 0; i < 8; i++) {
        const int dk = ty * 8 + i;
        const float rs = 1.f / ksb[dk];
#pragma unroll
        for (int j = 0; j < 8; j++)
            out[(size_t)dk * HD + tx * 8 + j] = acc[i][j] * rs;
    }
}

// sum 4 partials; output rounded to tf32 (feeds y GEMM)
__global__ void ctx_reduce(const float* __restrict__ cp, float* __restrict__ ctx) {
    const size_t i = (size_t)blockIdx.x * 256 + threadIdx.x;
    ctx[i] = f2tf32f(cp[i] + cp[i + 524288] + cp[i + 2 * 524288] + cp[i + 3 * 524288]);
}

// ---------------------------------------------------------------------------
// Launch
// ---------------------------------------------------------------------------
extern "C" void kernel_launch(void* const* d_in, const int* in_sizes, int n_in,
                              void* d_out, int out_size) {
    const float* x     = (const float*)d_in[0];
    const float* cond  = (const float*)d_in[1];
    const float* ln_g  = (const float*)d_in[2];
    const float* ln_b  = (const float*)d_in[3];
    const float* tln_g = (const float*)d_in[4];
    const float* tln_b = (const float*)d_in[5];
    const float* Wq    = (const float*)d_in[6];
    const float* bq    = (const float*)d_in[7];
    const float* Wk    = (const float*)d_in[8];
    const float* bk    = (const float*)d_in[9];
    const float* Wv    = (const float*)d_in[10];
    const float* bv    = (const float*)d_in[11];
    float* y = (float*)d_out;

    float* base = nullptr;
    cudaGetSymbolAddress((void**)&base, g_buf);
    float* xn  = base + OFF_XN;
    float* cn  = base + OFF_CN;
    float* q   = base + OFF_Q;
    float* kk  = base + OFF_K;
    float* vv  = base + OFF_V;
    float* km  = base + OFF_KM;
    float* ks  = base + OFF_KS;
    float* cp  = base + OFF_CP;
    float* ctx = base + OFF_CTX;
    float* wqr = base + OFF_WQR;
    float* wkr = base + OFF_WKR;
    float* wvr = base + OFF_WVR;

    cudaFuncSetAttribute(gemm_tf32<true>,
                         cudaFuncAttributeMaxDynamicSharedMemorySize, SMEM_BYTES);
    cudaFuncSetAttribute(gemm_tf32<false>,
                         cudaFuncAttributeMaxDynamicSharedMemorySize, SMEM_BYTES);

    // 0: pre-round weights to tf32 (2621440 floats / 4 / 256 = 2560 blocks)
    round_weights<<<2560, 256>>>(Wq, Wk, Wv, wqr);

    // 1-2: LayerNorms (outputs tf32-rounded)
    ln_kernel<DD><<<BB * TT, 256>>>(x, ln_g, ln_b, xn);
    ln_kernel<LL><<<BB * NN, 256>>>(cond, tln_g, tln_b, cn);

    // 3: q = softmax_head(xn @ Wq + bq), fused softmax, rounded output
    gemm_tf32<true><<<dim3(DD / 128, (BB * TT) / 128, 1), 256, SMEM_BYTES>>>(
        xn, wqr, bq, q, nullptr, nullptr, nullptr,
        DD, DD, DD, DD, 1, 0, 0, 0, 0, 0);

    // 4: k,v = cn @ W{k,v} + b fused in one launch
    gemm_tf32<false><<<dim3(2 * DD / 128, (BB * NN) / 128, 1), 256, SMEM_BYTES>>>(
        cn, wkr, bk, kk, wvr, bv, vv,
        LL, LL, DD, DD, 1, 0, 0, 0, 0, 0);

    // 5: k column softmax stats (over N)
    kcol_stats<<<BB * (DD / 32), 128>>>(kk, km, ks);

    // 6-7: context = softmax_N(k)^T @ v  (4-way N split + reduce, rounded)
    context_part<<<dim3(BB * HH, 4), 256>>>(kk, vv, km, ks, cp);
    ctx_reduce<<<(BB * HH * HD * HD) / 256, 256>>>(cp, ctx);

    // 8: y = q_soft @ ctx, batched over (b,h), writes d_out directly
    gemm_tf32<false><<<dim3(1, TT / 128, BB * HH), 256, SMEM_BYTES>>>(
        q, ctx, nullptr, y, nullptr, nullptr, nullptr,
        HD, DD, HD, DD,
        HH, (long long)TT * DD, HD, (long long)HD * HD,
        (long long)TT * DD, HD);
}

// round 8
// speedup vs baseline: 1.6152x; 1.6152x over previous
#include <cuda_runtime.h>
#include <cuda_fp16.h>
#include <cstdint>

// ---------------------------------------------------------------------------
// Problem constants (fixed shapes from reference setup_inputs)
// ---------------------------------------------------------------------------
#define BB   4
#define TT   4096
#define NN   512
#define DD   1024
#define LL   768
#define HH   8
#define HD   128

// ---------------------------------------------------------------------------
// Scratch (single __device__ array; offsets in floats)
// half arrays occupy (elems/2) float slots
// ---------------------------------------------------------------------------
#define OFF_XN   0LL                                 // half [B*T,D]  -> 8388608 f
#define OFF_CN   (OFF_XN + 8388608LL)                // half [B*N,L]  ->  786432 f
#define OFF_Q    (OFF_CN + 786432LL)                 // half [B*T,D]  -> 8388608 f
#define OFF_K    (OFF_Q  + 8388608LL)                // f32  [B*N,D]  -> 2097152 f
#define OFF_V    (OFF_K  + 2097152LL)                // f32  [B*N,D]  -> 2097152 f
#define OFF_KM   (OFF_V  + 2097152LL)                // f32  [B,D]
#define OFF_KS   (OFF_KM + 4096LL)                   // f32  [B,D]
#define OFF_CP   (OFF_KS + 4096LL)                   // f32  [4,B*H,128,128]
#define OFF_CTX  (OFF_CP + 2097152LL)                // half [B*H,dk,dv] -> 262144 f
#define OFF_WQ16 (OFF_CTX + 262144LL)                // half [1024,1024] -> 524288 f
#define OFF_WK16 (OFF_WQ16 + 524288LL)               // half [768,1024]  -> 393216 f
#define OFF_WV16 (OFF_WK16 + 393216LL)               // half [768,1024]  -> 393216 f
#define SCRATCH_TOTAL (OFF_WV16 + 393216LL)

__device__ __align__(256) float g_buf[SCRATCH_TOTAL];

// ---------------------------------------------------------------------------
// Helpers
// ---------------------------------------------------------------------------
__device__ __forceinline__ void mma_fp16(float* c, const uint32_t* a, const uint32_t* b) {
    asm volatile(
        "mma.sync.aligned.m16n8k16.row.col.f32.f16.f16.f32 "
        "{%0,%1,%2,%3}, {%4,%5,%6,%7}, {%8,%9}, {%0,%1,%2,%3};\n"
        : "+f"(c[0]), "+f"(c[1]), "+f"(c[2]), "+f"(c[3])
        : "r"(a[0]), "r"(a[1]), "r"(a[2]), "r"(a[3]),
          "r"(b[0]), "r"(b[1]));
}

__device__ __forceinline__ void ldsm4(uint32_t& r0, uint32_t& r1, uint32_t& r2,
                                      uint32_t& r3, uint32_t addr) {
    asm volatile("ldmatrix.sync.aligned.m8n8.x4.shared.b16 {%0,%1,%2,%3}, [%4];\n"
                 : "=r"(r0), "=r"(r1), "=r"(r2), "=r"(r3) : "r"(addr));
}

__device__ __forceinline__ void ldsm4t(uint32_t& r0, uint32_t& r1, uint32_t& r2,
                                       uint32_t& r3, uint32_t addr) {
    asm volatile("ldmatrix.sync.aligned.m8n8.x4.trans.shared.b16 {%0,%1,%2,%3}, [%4];\n"
                 : "=r"(r0), "=r"(r1), "=r"(r2), "=r"(r3) : "r"(addr));
}

__device__ __forceinline__ void cp16(void* s, const void* g) {
    uint32_t sa = (uint32_t)__cvta_generic_to_shared(s);
    asm volatile("cp.async.cg.shared.global [%0], [%1], 16;\n" :: "r"(sa), "l"(g));
}

// ---------------------------------------------------------------------------
// Convert weights f32 -> f16 (layout kept [K, N])
// ---------------------------------------------------------------------------
__global__ void conv_weights(const float* __restrict__ wq, const float* __restrict__ wk,
                             const float* __restrict__ wv, __half* __restrict__ out) {
    const size_t fi = ((size_t)blockIdx.x * 256 + threadIdx.x) * 4;
    const float* src;
    size_t off;
    if (fi < 1048576) { src = wq; off = fi; }
    else if (fi < 1048576 + 786432) { src = wk; off = fi - 1048576; }
    else { src = wv; off = fi - (1048576 + 786432); }
    float4 v = *(const float4*)(src + off);
    *(half2*)(out + fi) = __floats2half2_rn(v.x, v.y);
    *(half2*)(out + fi + 2) = __floats2half2_rn(v.z, v.w);
}

// ---------------------------------------------------------------------------
// LayerNorm: one block per row, fp16 output (GEMM operand)
// ---------------------------------------------------------------------------
template <int DIM>
__global__ void ln_kernel(const float* __restrict__ x, const float* __restrict__ g,
                          const float* __restrict__ bta, __half* __restrict__ out) {
    constexpr int PER = DIM / 256;
    const size_t row = blockIdx.x;
    const float* xr = x + row * DIM;
    float v[PER];
    float s = 0.f, sq = 0.f;
#pragma unroll
    for (int i = 0; i < PER; i++) {
        v[i] = xr[threadIdx.x + 256 * i];
        s += v[i];
        sq += v[i] * v[i];
    }
#pragma unroll
    for (int o = 16; o; o >>= 1) {
        s += __shfl_xor_sync(0xffffffffu, s, o);
        sq += __shfl_xor_sync(0xffffffffu, sq, o);
    }
    __shared__ float sm[8], sv[8];
    int w = threadIdx.x >> 5;
    if ((threadIdx.x & 31) == 0) { sm[w] = s; sv[w] = sq; }
    __syncthreads();
    if (threadIdx.x < 32) {
        s = (threadIdx.x < 8) ? sm[threadIdx.x] : 0.f;
        sq = (threadIdx.x < 8) ? sv[threadIdx.x] : 0.f;
#pragma unroll
        for (int o = 4; o; o >>= 1) {
            s += __shfl_xor_sync(0xffffffffu, s, o);
            sq += __shfl_xor_sync(0xffffffffu, sq, o);
        }
        if (threadIdx.x == 0) { sm[0] = s; sv[0] = sq; }
    }
    __syncthreads();
    const float mean = sm[0] * (1.f / DIM);
    const float var = sv[0] * (1.f / DIM) - mean * mean;
    const float rstd = rsqrtf(var + 1e-5f);
    __half* orow = out + row * DIM;
#pragma unroll
    for (int i = 0; i < PER; i++) {
        int c = threadIdx.x + 256 * i;
        orow[c] = __float2half_rn((v[i] - mean) * rstd * g[c] + bta[c]);
    }
}

// ---------------------------------------------------------------------------
// fp16 tensor-core GEMM: C[M,N] = A[M,K] @ W[K,N] (+bias), f32 accumulate
// 128x128 tile, BK=32, cp.async 4-stage pipeline, 2 CTAs/SM.
// 8 warps (2m x 4n), warp tile 64x32 -> 4x4 m16n8k16 per 16-k step.
// A frags: ldmatrix.x4 ; B frags: ldmatrix.x4.trans on [k][n] smem.
// FUSE_SM: row softmax over the 128-col tile (== one head), fp16 output.
// Dual (Bm2!=null): grid.x split between {Bm,bias,C} and {Bm2,bias2,C2}.
// ---------------------------------------------------------------------------
#define STAGES 4
#define AS_H 40              // halves per A smem row (32 + 8 pad)
#define BS_H 136             // halves per B smem row (128 + 8 pad)
#define A_ST_H (128 * AS_H)  // 5120 halves
#define B_ST_H (32 * BS_H)   // 4352 halves
#define SMEM_BYTES (STAGES * (A_ST_H + B_ST_H) * 2)   // 75776

template <bool FUSE_SM, typename OutT>
__global__ void __launch_bounds__(256, 2)
gemm_fp16(const __half* __restrict__ A, const __half* __restrict__ Bm,
          const float* __restrict__ bias, OutT* __restrict__ C,
          const __half* __restrict__ Bm2, const float* __restrict__ bias2,
          OutT* __restrict__ C2,
          int K, int lda, int ldb, int ldc,
          int Hdiv, long long sA0, long long sA1, long long sB,
          long long sC0, long long sC1) {
    extern __shared__ __align__(16) char smraw[];
    __half* Asm = (__half*)smraw;
    __half* Bsm = Asm + STAGES * A_ST_H;

    int tN;
    if (Bm2 != nullptr) {
        const int half_g = gridDim.x >> 1;
        if (blockIdx.x >= half_g) {
            Bm = Bm2; bias = bias2; C = C2;
            tN = (blockIdx.x - half_g) * 128;
        } else {
            tN = blockIdx.x * 128;
        }
    } else {
        const int z = blockIdx.z;
        const int zb = z / Hdiv, zh = z - zb * Hdiv;
        A += zb * sA0 + zh * sA1;
        Bm += (long long)z * sB;
        C += zb * sC0 + zh * sC1;
        tN = blockIdx.x * 128;
    }
    const int tM = blockIdx.y * 128;
    const int tid = threadIdx.x;
    const int lane = tid & 31, warp = tid >> 5;
    const int m_base = (warp & 1) * 64;
    const int n_base = (warp >> 1) * 32;

    const __half* Ag = A + (size_t)tM * lda;
    const __half* Bg = Bm + tN;
    const int nk = K >> 5;   // BK = 32

    // producers: A 128x32 halves = 512 16B-chunks; B 32x128 = 512 chunks
    const int ar = tid >> 1;               // with j: ci = tid + 256j -> r=ci>>2
    (void)ar;

    auto issue = [&](int kt) {
        const int st = kt & (STAGES - 1);
        __half* Al = Asm + st * A_ST_H;
        __half* Bl = Bsm + st * B_ST_H;
        const int k0 = kt << 5;
#pragma unroll
        for (int j = 0; j < 2; j++) {
            const int ci = tid + 256 * j;
            const int r = ci >> 2, c = (ci & 3) * 8;
            cp16(Al + r * AS_H + c, Ag + (size_t)r * lda + k0 + c);
        }
#pragma unroll
        for (int j = 0; j < 2; j++) {
            const int ci = tid + 256 * j;
            const int r = ci >> 4, c = (ci & 15) * 8;
            cp16(Bl + r * BS_H + c, Bg + (size_t)(k0 + r) * ldb + c);
        }
    };

    // per-lane ldmatrix offsets (bytes)
    const uint32_t asm_u32 = (uint32_t)__cvta_generic_to_shared(Asm);
    const uint32_t bsm_u32 = (uint32_t)__cvta_generic_to_shared(Bsm);
    const uint32_t a_lane = (uint32_t)(((lane & 15) * AS_H + (lane >> 4) * 8) * 2);
    const uint32_t b_lane = (uint32_t)(((lane & 15) * BS_H + (lane >> 4) * 8) * 2);

    float acc[4][4][4];
#pragma unroll
    for (int i = 0; i < 4; i++)
#pragma unroll
        for (int j = 0; j < 4; j++)
#pragma unroll
            for (int r = 0; r < 4; r++) acc[i][j][r] = 0.f;

#pragma unroll
    for (int s = 0; s < STAGES - 1; s++) {
        issue(s);   // nk >= 4 >= STAGES-1 for all launches here
        asm volatile("cp.async.commit_group;\n");
    }

    for (int kt = 0; kt < nk; kt++) {
        if (kt + STAGES - 1 < nk) issue(kt + STAGES - 1);
        asm volatile("cp.async.commit_group;\n");
        asm volatile("cp.async.wait_group %0;\n" :: "n"(STAGES - 1));
        __syncthreads();

        const int st = kt & (STAGES - 1);
        const uint32_t a_st = asm_u32 + (uint32_t)(st * A_ST_H * 2) + a_lane;
        const uint32_t b_st = bsm_u32 + (uint32_t)(st * B_ST_H * 2) + b_lane;
#pragma unroll
        for (int kk = 0; kk < 2; kk++) {
            uint32_t af[4][4];
#pragma unroll
            for (int im = 0; im < 4; im++)
                ldsm4(af[im][0], af[im][1], af[im][2], af[im][3],
                      a_st + (uint32_t)(((m_base + im * 16) * AS_H + kk * 16) * 2));
            uint32_t bf[2][4];
#pragma unroll
            for (int t = 0; t < 2; t++)
                ldsm4t(bf[t][0], bf[t][1], bf[t][2], bf[t][3],
                       b_st + (uint32_t)((kk * 16 * BS_H + n_base + t * 16) * 2));
#pragma unroll
            for (int im = 0; im < 4; im++)
#pragma unroll
                for (int in = 0; in < 4; in++)
                    mma_fp16(acc[im][in], af[im], &bf[in >> 1][(in & 1) * 2]);
        }
        __syncthreads();
    }

    // -------- epilogue --------
    float b0[4], b1[4];
#pragma unroll
    for (int in = 0; in < 4; in++) {
        if (bias != nullptr) {
            const int c = tN + n_base + in * 8 + 2 * (lane & 3);
            b0[in] = __ldg(bias + c);
            b1[in] = __ldg(bias + c + 1);
        } else { b0[in] = 0.f; b1[in] = 0.f; }
    }
#pragma unroll
    for (int im = 0; im < 4; im++)
#pragma unroll
        for (int in = 0; in < 4; in++) {
            acc[im][in][0] += b0[in];
            acc[im][in][1] += b1[in];
            acc[im][in][2] += b0[in];
            acc[im][in][3] += b1[in];
        }

    if (FUSE_SM) {
        float* red = (float*)smraw;
        float* red2 = red + 512;
        const int wn = warp >> 1;

        float m0[4], m1[4];
#pragma unroll
        for (int im = 0; im < 4; im++) {
            float a = -1e30f, b = -1e30f;
#pragma unroll
            for (int in = 0; in < 4; in++) {
                a = fmaxf(a, fmaxf(acc[im][in][0], acc[im][in][1]));
                b = fmaxf(b, fmaxf(acc[im][in][2], acc[im][in][3]));
            }
            a = fmaxf(a, __shfl_xor_sync(0xffffffffu, a, 1));
            a = fmaxf(a, __shfl_xor_sync(0xffffffffu, a, 2));
            b = fmaxf(b, __shfl_xor_sync(0xffffffffu, b, 1));
            b = fmaxf(b, __shfl_xor_sync(0xffffffffu, b, 2));
            m0[im] = a; m1[im] = b;
        }
        if ((lane & 3) == 0) {
#pragma unroll
            for (int im = 0; im < 4; im++) {
                const int r = m_base + im * 16 + (lane >> 2);
                red[r * 4 + wn] = m0[im];
                red[(r + 8) * 4 + wn] = m1[im];
            }
        }
        __syncthreads();
        float M0[4], M1[4];
#pragma unroll
        for (int im = 0; im < 4; im++) {
            const int r = m_base + im * 16 + (lane >> 2);
            M0[im] = fmaxf(fmaxf(red[r * 4], red[r * 4 + 1]),
                           fmaxf(red[r * 4 + 2], red[r * 4 + 3]));
            M1[im] = fmaxf(fmaxf(red[(r + 8) * 4], red[(r + 8) * 4 + 1]),
                           fmaxf(red[(r + 8) * 4 + 2], red[(r + 8) * 4 + 3]));
        }
        float s0[4], s1[4];
#pragma unroll
        for (int im = 0; im < 4; im++) {
            float sa = 0.f, sb = 0.f;
#pragma unroll
            for (int in = 0; in < 4; in++) {
                acc[im][in][0] = __expf(acc[im][in][0] - M0[im]);
                acc[im][in][1] = __expf(acc[im][in][1] - M0[im]);
                acc[im][in][2] = __expf(acc[im][in][2] - M1[im]);
                acc[im][in][3] = __expf(acc[im][in][3] - M1[im]);
                sa += acc[im][in][0] + acc[im][in][1];
                sb += acc[im][in][2] + acc[im][in][3];
            }
            sa += __shfl_xor_sync(0xffffffffu, sa, 1);
            sa += __shfl_xor_sync(0xffffffffu, sa, 2);
            sb += __shfl_xor_sync(0xffffffffu, sb, 1);
            sb += __shfl_xor_sync(0xffffffffu, sb, 2);
            s0[im] = sa; s1[im] = sb;
        }
        if ((lane & 3) == 0) {
#pragma unroll
            for (int im = 0; im < 4; im++) {
                const int r = m_base + im * 16 + (lane >> 2);
                red2[r * 4 + wn] = s0[im];
                red2[(r + 8) * 4 + wn] = s1[im];
            }
        }
        __syncthreads();
#pragma unroll
        for (int im = 0; im < 4; im++) {
            const int r = m_base + im * 16 + (lane >> 2);
            const float inv0 = 1.f / (red2[r * 4] + red2[r * 4 + 1] +
                                      red2[r * 4 + 2] + red2[r * 4 + 3]);
            const float inv1 = 1.f / (red2[(r + 8) * 4] + red2[(r + 8) * 4 + 1] +
                                      red2[(r + 8) * 4 + 2] + red2[(r + 8) * 4 + 3]);
            const int r0 = tM + r;
#pragma unroll
            for (int in = 0; in < 4; in++) {
                const int c = tN + n_base + in * 8 + 2 * (lane & 3);
                *(half2*)((__half*)C + (size_t)r0 * ldc + c) =
                    __floats2half2_rn(acc[im][in][0] * inv0, acc[im][in][1] * inv0);
                *(half2*)((__half*)C + (size_t)(r0 + 8) * ldc + c) =
                    __floats2half2_rn(acc[im][in][2] * inv1, acc[im][in][3] * inv1);
            }
        }
    } else {
#pragma unroll
        for (int im = 0; im < 4; im++) {
            const int r0 = tM + m_base + im * 16 + (lane >> 2);
#pragma unroll
            for (int in = 0; in < 4; in++) {
                const int c = tN + n_base + in * 8 + 2 * (lane & 3);
                *(float2*)((float*)C + (size_t)r0 * ldc + c) =
                    make_float2(acc[im][in][0], acc[im][in][1]);
                *(float2*)((float*)C + (size_t)(r0 + 8) * ldc + c) =
                    make_float2(acc[im][in][2], acc[im][in][3]);
            }
        }
    }
}

// ---------------------------------------------------------------------------
// k column softmax stats (max, sumexp over N=512 per (b, d) column)
// ---------------------------------------------------------------------------
__global__ void kcol_stats(const float* __restrict__ k, float* __restrict__ om,
                           float* __restrict__ os) {
    const int b = blockIdx.x >> 5;
    const int cg = blockIdx.x & 31;
    const int cl = threadIdx.x & 31;
    const int seg = threadIdx.x >> 5;
    const int col = cg * 32 + cl;
    const float* p = k + (size_t)b * NN * DD + col;

    float m = -1e30f;
#pragma unroll 4
    for (int i = 0; i < 128; i++) m = fmaxf(m, p[(size_t)(seg * 128 + i) * DD]);

    __shared__ float smx[4][32], ssm[4][32], gmx[32];
    smx[seg][cl] = m;
    __syncthreads();
    if (seg == 0) {
        float M = fmaxf(fmaxf(smx[0][cl], smx[1][cl]), fmaxf(smx[2][cl], smx[3][cl]));
        gmx[cl] = M;
    }
    __syncthreads();
    const float M = gmx[cl];
    float s = 0.f;
#pragma unroll 4
    for (int i = 0; i < 128; i++) s += __expf(p[(size_t)(seg * 128 + i) * DD] - M);
    ssm[seg][cl] = s;
    __syncthreads();
    if (seg == 0) {
        float S = ssm[0][cl] + ssm[1][cl] + ssm[2][cl] + ssm[3][cl];
        om[b * DD + col] = M;
        os[b * DD + col] = S;
    }
}

// ---------------------------------------------------------------------------
// context partials: cp[split,bh,dk,dv] = (1/s_dk) * sum_n exp(k-m_dk) * v
// ---------------------------------------------------------------------------
__global__ void __launch_bounds__(256)
context_part(const float* __restrict__ k, const float* __restrict__ v,
             const float* __restrict__ km, const float* __restrict__ ks,
             float* __restrict__ cp) {
    const int bh = blockIdx.x;
    const int b = bh >> 3, h = bh & 7;
    const int split = blockIdx.y;
    __shared__ float Ks[32][132], Vs[32][132];

    const float* kb = k + (size_t)b * NN * DD + h * HD;
    const float* vb = v + (size_t)b * NN * DD + h * HD;
    const float* kmb = km + b * DD + h * HD;
    const float* ksb = ks + b * DD + h * HD;

    float acc[8][8];
#pragma unroll
    for (int i = 0; i < 8; i++)
#pragma unroll
        for (int j = 0; j < 8; j++) acc[i][j] = 0.f;

    const int tx = threadIdx.x & 15, ty = threadIdx.x >> 4;

    for (int c = 0; c < 4; c++) {
        const int n0 = split * 128 + c * 32;
        for (int t = threadIdx.x; t < 32 * 128; t += 256) {
            int nn = t >> 7, dd = t & 127;
            Ks[nn][dd] = __expf(kb[(size_t)(n0 + nn) * DD + dd] - kmb[dd]);
            Vs[nn][dd] = vb[(size_t)(n0 + nn) * DD + dd];
        }
        __syncthreads();
#pragma unroll 8
        for (int nn = 0; nn < 32; nn++) {
            float kr[8], vr[8];
#pragma unroll
            for (int i = 0; i < 8; i++) kr[i] = Ks[nn][ty * 8 + i];
#pragma unroll
            for (int j = 0; j < 8; j++) vr[j] = Vs[nn][tx * 8 + j];
#pragma unroll
            for (int i = 0; i < 8; i++)
#pragma unroll
                for (int j = 0; j < 8; j++) acc[i][j] += kr[i] * vr[j];
        }
        __syncthreads();
    }

    float* out = cp + ((size_t)split * 32 + bh) * (HD * HD);
#pragma unroll
    for (int i = 0; i < 8; i++) {
        const int dk = ty * 8 + i;
        const float rs = 1.f / ksb[dk];
#pragma unroll
        for (int j = 0; j < 8; j++)
            out[(size_t)dk * HD + tx * 8 + j] = acc[i][j] * rs;
    }
}

// sum 4 partials; fp16 output [bh][dk][dv] (B operand of y GEMM)
__global__ void ctx_reduce(const float* __restrict__ cp, __half* __restrict__ ctx) {
    const size_t i = (size_t)blockIdx.x * 256 + threadIdx.x;
    ctx[i] = __float2half_rn(cp[i] + cp[i + 524288] +
                             cp[i + 2 * 524288] + cp[i + 3 * 524288]);
}

// ---------------------------------------------------------------------------
// Launch
// ---------------------------------------------------------------------------
extern "C" void kernel_launch(void* const* d_in, const int* in_sizes, int n_in,
                              void* d_out, int out_size) {
    const float* x     = (const float*)d_in[0];
    const float* cond  = (const float*)d_in[1];
    const float* ln_g  = (const float*)d_in[2];
    const float* ln_b  = (const float*)d_in[3];
    const float* tln_g = (const float*)d_in[4];
    const float* tln_b = (const float*)d_in[5];
    const float* Wq    = (const float*)d_in[6];
    const float* bq    = (const float*)d_in[7];
    const float* Wk    = (const float*)d_in[8];
    const float* bk    = (const float*)d_in[9];
    const float* Wv    = (const float*)d_in[10];
    const float* bv    = (const float*)d_in[11];
    float* y = (float*)d_out;

    float* base = nullptr;
    cudaGetSymbolAddress((void**)&base, g_buf);
    __half* xn   = (__half*)(base + OFF_XN);
    __half* cn   = (__half*)(base + OFF_CN);
    __half* q    = (__half*)(base + OFF_Q);
    float*  kk   = base + OFF_K;
    float*  vv   = base + OFF_V;
    float*  km   = base + OFF_KM;
    float*  ks   = base + OFF_KS;
    float*  cp   = base + OFF_CP;
    __half* ctx  = (__half*)(base + OFF_CTX);
    __half* wq16 = (__half*)(base + OFF_WQ16);
    __half* wk16 = (__half*)(base + OFF_WK16);
    __half* wv16 = (__half*)(base + OFF_WV16);

    cudaFuncSetAttribute(gemm_fp16<true, __half>,
                         cudaFuncAttributeMaxDynamicSharedMemorySize, SMEM_BYTES);
    cudaFuncSetAttribute(gemm_fp16<false, float>,
                         cudaFuncAttributeMaxDynamicSharedMemorySize, SMEM_BYTES);

    // 0: convert weights to fp16 (layout [K, N] kept)
    conv_weights<<<2560, 256>>>(Wq, Wk, Wv, wq16);

    // 1-2: LayerNorms (fp16 outputs)
    ln_kernel<DD><<<BB * TT, 256>>>(x, ln_g, ln_b, xn);
    ln_kernel<LL><<<BB * NN, 256>>>(cond, tln_g, tln_b, cn);

    // 3: q = softmax_head(xn @ Wq + bq), fused softmax, fp16 output
    gemm_fp16<true, __half><<<dim3(DD / 128, (BB * TT) / 128, 1), 256, SMEM_BYTES>>>(
        xn, wq16, bq, q, nullptr, nullptr, nullptr,
        DD, DD, DD, DD, 1, 0, 0, 0, 0, 0);

    // 4: k,v = cn @ W{k,v} + b fused in one launch (f32 outputs)
    gemm_fp16<false, float><<<dim3(2 * DD / 128, (BB * NN) / 128, 1), 256, SMEM_BYTES>>>(
        cn, wk16, bk, kk, wv16, bv, vv,
        LL, LL, DD, DD, 1, 0, 0, 0, 0, 0);

    // 5: k column softmax stats (over N)
    kcol_stats<<<BB * (DD / 32), 128>>>(kk, km, ks);

    // 6-7: context = softmax_N(k)^T @ v  (4-way N split + fp16 reduce)
    context_part<<<dim3(BB * HH, 4), 256>>>(kk, vv, km, ks, cp);
    ctx_reduce<<<(BB * HH * HD * HD) / 256, 256>>>(cp, ctx);

    // 8: y = q_soft @ ctx, batched over (b,h), writes d_out (f32)
    gemm_fp16<false, float><<<dim3(1, TT / 128, BB * HH), 256, SMEM_BYTES>>>(
        q, ctx, nullptr, y, nullptr, nullptr, nullptr,
        HD, DD, HD, DD,
        HH, (long long)TT * DD, HD, (long long)HD * HD,
        (long long)TT * DD, HD);
}

// round 9
// speedup vs baseline: 1.6388x; 1.0146x over previous
#include <cuda_runtime.h>
#include <cuda_fp16.h>
#include <cstdint>

// ---------------------------------------------------------------------------
// Problem constants (fixed shapes from reference setup_inputs)
// ---------------------------------------------------------------------------
#define BB   4
#define TT   4096
#define NN   512
#define DD   1024
#define LL   768
#define HH   8
#define HD   128

// ---------------------------------------------------------------------------
// Scratch (single __device__ array; offsets in floats)
// ---------------------------------------------------------------------------
#define OFF_XN   0LL                                 // half [B*T,D]
#define OFF_CN   (OFF_XN + 8388608LL)                // half [B*N,L]
#define OFF_Q    (OFF_CN + 786432LL)                 // half [B*T,D]
#define OFF_K    (OFF_Q  + 8388608LL)                // f32  [B*N,D]
#define OFF_V    (OFF_K  + 2097152LL)                // f32  [B*N,D]
#define OFF_KM   (OFF_V  + 2097152LL)                // f32  [B,D]
#define OFF_KS   (OFF_KM + 4096LL)                   // f32  [B,D]
#define OFF_CP   (OFF_KS + 4096LL)                   // f32  [4,B*H,128,128]
#define OFF_CTX  (OFF_CP + 2097152LL)                // half [B*H,dk,dv]
#define OFF_WQ16 (OFF_CTX + 262144LL)                // half [1024,1024]
#define OFF_WK16 (OFF_WQ16 + 524288LL)               // half [768,1024]
#define OFF_WV16 (OFF_WK16 + 393216LL)               // half [768,1024]
#define SCRATCH_TOTAL (OFF_WV16 + 393216LL)

__device__ __align__(256) float g_buf[SCRATCH_TOTAL];

// ---------------------------------------------------------------------------
// Helpers
// ---------------------------------------------------------------------------
__device__ __forceinline__ void mma_fp16(float* c, const uint32_t* a, const uint32_t* b) {
    asm volatile(
        "mma.sync.aligned.m16n8k16.row.col.f32.f16.f16.f32 "
        "{%0,%1,%2,%3}, {%4,%5,%6,%7}, {%8,%9}, {%0,%1,%2,%3};\n"
        : "+f"(c[0]), "+f"(c[1]), "+f"(c[2]), "+f"(c[3])
        : "r"(a[0]), "r"(a[1]), "r"(a[2]), "r"(a[3]),
          "r"(b[0]), "r"(b[1]));
}

__device__ __forceinline__ void ldsm4(uint32_t& r0, uint32_t& r1, uint32_t& r2,
                                      uint32_t& r3, uint32_t addr) {
    asm volatile("ldmatrix.sync.aligned.m8n8.x4.shared.b16 {%0,%1,%2,%3}, [%4];\n"
                 : "=r"(r0), "=r"(r1), "=r"(r2), "=r"(r3) : "r"(addr));
}

__device__ __forceinline__ void ldsm4t(uint32_t& r0, uint32_t& r1, uint32_t& r2,
                                       uint32_t& r3, uint32_t addr) {
    asm volatile("ldmatrix.sync.aligned.m8n8.x4.trans.shared.b16 {%0,%1,%2,%3}, [%4];\n"
                 : "=r"(r0), "=r"(r1), "=r"(r2), "=r"(r3) : "r"(addr));
}

__device__ __forceinline__ void cp16(void* s, const void* g) {
    uint32_t sa = (uint32_t)__cvta_generic_to_shared(s);
    asm volatile("cp.async.cg.shared.global [%0], [%1], 16;\n" :: "r"(sa), "l"(g));
}

// ---------------------------------------------------------------------------
// Convert weights f32 -> f16 (layout kept [K, N])
// ---------------------------------------------------------------------------
__global__ void conv_weights(const float* __restrict__ wq, const float* __restrict__ wk,
                             const float* __restrict__ wv, __half* __restrict__ out) {
    const size_t fi = ((size_t)blockIdx.x * 256 + threadIdx.x) * 4;
    const float* src;
    size_t off;
    if (fi < 1048576) { src = wq; off = fi; }
    else if (fi < 1048576 + 786432) { src = wk; off = fi - 1048576; }
    else { src = wv; off = fi - (1048576 + 786432); }
    float4 v = *(const float4*)(src + off);
    *(half2*)(out + fi) = __floats2half2_rn(v.x, v.y);
    *(half2*)(out + fi + 2) = __floats2half2_rn(v.z, v.w);
}

// ---------------------------------------------------------------------------
// LayerNorm: one block per row, fp16 output (GEMM operand)
// ---------------------------------------------------------------------------
template <int DIM>
__global__ void ln_kernel(const float* __restrict__ x, const float* __restrict__ g,
                          const float* __restrict__ bta, __half* __restrict__ out) {
    constexpr int PER = DIM / 256;
    const size_t row = blockIdx.x;
    const float* xr = x + row * DIM;
    float v[PER];
    float s = 0.f, sq = 0.f;
#pragma unroll
    for (int i = 0; i < PER; i++) {
        v[i] = xr[threadIdx.x + 256 * i];
        s += v[i];
        sq += v[i] * v[i];
    }
#pragma unroll
    for (int o = 16; o; o >>= 1) {
        s += __shfl_xor_sync(0xffffffffu, s, o);
        sq += __shfl_xor_sync(0xffffffffu, sq, o);
    }
    __shared__ float sm[8], sv[8];
    int w = threadIdx.x >> 5;
    if ((threadIdx.x & 31) == 0) { sm[w] = s; sv[w] = sq; }
    __syncthreads();
    if (threadIdx.x < 32) {
        s = (threadIdx.x < 8) ? sm[threadIdx.x] : 0.f;
        sq = (threadIdx.x < 8) ? sv[threadIdx.x] : 0.f;
#pragma unroll
        for (int o = 4; o; o >>= 1) {
            s += __shfl_xor_sync(0xffffffffu, s, o);
            sq += __shfl_xor_sync(0xffffffffu, sq, o);
        }
        if (threadIdx.x == 0) { sm[0] = s; sv[0] = sq; }
    }
    __syncthreads();
    const float mean = sm[0] * (1.f / DIM);
    const float var = sv[0] * (1.f / DIM) - mean * mean;
    const float rstd = rsqrtf(var + 1e-5f);
    __half* orow = out + row * DIM;
#pragma unroll
    for (int i = 0; i < PER; i++) {
        int c = threadIdx.x + 256 * i;
        orow[c] = __float2half_rn((v[i] - mean) * rstd * g[c] + bta[c]);
    }
}

// ---------------------------------------------------------------------------
// fp16 tensor-core GEMM: C[M,N] = A[M,K] @ W[K,N] (+bias), f32 accumulate
// 128x128 tile, BK=64, cp.async 3-stage pipeline, ONE barrier per k-iter.
// 8 warps (2m x 4n), warp tile 64x32 -> 4x4 m16n8k16 per 16-k step (x4 steps).
// A frags: ldmatrix.x4 ; B frags: ldmatrix.x4.trans on [k][n] smem.
// FUSE_SM: row softmax over the 128-col tile (== one head), fp16 output.
// Dual (Bm2!=null): grid.x split between {Bm,bias,C} and {Bm2,bias2,C2}.
// ---------------------------------------------------------------------------
#define STAGES 3
#define AS_H 72              // halves per A smem row (64 + 8 pad)
#define BS_H 136             // halves per B smem row (128 + 8 pad)
#define A_ST_H (128 * AS_H)  // 9216 halves
#define B_ST_H (64 * BS_H)   // 8704 halves
#define SMEM_BYTES (STAGES * (A_ST_H + B_ST_H) * 2)   // 107520

template <bool FUSE_SM, typename OutT>
__global__ void __launch_bounds__(256, 2)
gemm_fp16(const __half* __restrict__ A, const __half* __restrict__ Bm,
          const float* __restrict__ bias, OutT* __restrict__ C,
          const __half* __restrict__ Bm2, const float* __restrict__ bias2,
          OutT* __restrict__ C2,
          int K, int lda, int ldb, int ldc,
          int Hdiv, long long sA0, long long sA1, long long sB,
          long long sC0, long long sC1) {
    extern __shared__ __align__(16) char smraw[];
    __half* Asm = (__half*)smraw;
    __half* Bsm = Asm + STAGES * A_ST_H;

    int tN;
    if (Bm2 != nullptr) {
        const int half_g = gridDim.x >> 1;
        if (blockIdx.x >= half_g) {
            Bm = Bm2; bias = bias2; C = C2;
            tN = (blockIdx.x - half_g) * 128;
        } else {
            tN = blockIdx.x * 128;
        }
    } else {
        const int z = blockIdx.z;
        const int zb = z / Hdiv, zh = z - zb * Hdiv;
        A += zb * sA0 + zh * sA1;
        Bm += (long long)z * sB;
        C += zb * sC0 + zh * sC1;
        tN = blockIdx.x * 128;
    }
    const int tM = blockIdx.y * 128;
    const int tid = threadIdx.x;
    const int lane = tid & 31, warp = tid >> 5;
    const int m_base = (warp & 1) * 64;
    const int n_base = (warp >> 1) * 32;

    const __half* Ag = A + (size_t)tM * lda;
    const __half* Bg = Bm + tN;
    const int nk = K >> 6;   // BK = 64  (nk >= 2 for all launches here)

    auto issue = [&](int kt) {
        const int st = kt % STAGES;
        __half* Al = Asm + st * A_ST_H;
        __half* Bl = Bsm + st * B_ST_H;
        const int k0 = kt << 6;
#pragma unroll
        for (int j = 0; j < 4; j++) {        // A: 128 rows x 64 halves
            const int ci = tid + 256 * j;
            const int r = ci >> 3, c = (ci & 7) * 8;
            cp16(Al + r * AS_H + c, Ag + (size_t)r * lda + k0 + c);
        }
#pragma unroll
        for (int j = 0; j < 4; j++) {        // B: 64 rows x 128 halves
            const int ci = tid + 256 * j;
            const int r = ci >> 4, c = (ci & 15) * 8;
            cp16(Bl + r * BS_H + c, Bg + (size_t)(k0 + r) * ldb + c);
        }
    };

    // per-lane ldmatrix offsets (bytes)
    const uint32_t asm_u32 = (uint32_t)__cvta_generic_to_shared(Asm);
    const uint32_t bsm_u32 = (uint32_t)__cvta_generic_to_shared(Bsm);
    const uint32_t a_lane = (uint32_t)(((lane & 15) * AS_H + (lane >> 4) * 8) * 2);
    const uint32_t b_lane = (uint32_t)(((lane & 15) * BS_H + (lane >> 4) * 8) * 2);

    float acc[4][4][4];
#pragma unroll
    for (int i = 0; i < 4; i++)
#pragma unroll
        for (int j = 0; j < 4; j++)
#pragma unroll
            for (int r = 0; r < 4; r++) acc[i][j][r] = 0.f;

    issue(0);
    asm volatile("cp.async.commit_group;\n");
    issue(1);
    asm volatile("cp.async.commit_group;\n");

    for (int kt = 0; kt < nk; kt++) {
        asm volatile("cp.async.wait_group %0;\n" :: "n"(1));
        __syncthreads();
        // safe: stage (kt+2)%3 == (kt-1)%3, consumed before this barrier
        if (kt + 2 < nk) issue(kt + 2);
        asm volatile("cp.async.commit_group;\n");

        const int st = kt % STAGES;
        const uint32_t a_st = asm_u32 + (uint32_t)(st * A_ST_H * 2) + a_lane;
        const uint32_t b_st = bsm_u32 + (uint32_t)(st * B_ST_H * 2) + b_lane;
#pragma unroll
        for (int kk = 0; kk < 4; kk++) {
            uint32_t af[4][4];
#pragma unroll
            for (int im = 0; im < 4; im++)
                ldsm4(af[im][0], af[im][1], af[im][2], af[im][3],
                      a_st + (uint32_t)(((m_base + im * 16) * AS_H + kk * 16) * 2));
            uint32_t bf[2][4];
#pragma unroll
            for (int t = 0; t < 2; t++)
                ldsm4t(bf[t][0], bf[t][1], bf[t][2], bf[t][3],
                       b_st + (uint32_t)((kk * 16 * BS_H + n_base + t * 16) * 2));
#pragma unroll
            for (int im = 0; im < 4; im++)
#pragma unroll
                for (int in = 0; in < 4; in++)
                    mma_fp16(acc[im][in], af[im], &bf[in >> 1][(in & 1) * 2]);
        }
    }
    __syncthreads();   // protect smem reuse in FUSE epilogue

    // -------- epilogue --------
    float b0[4], b1[4];
#pragma unroll
    for (int in = 0; in < 4; in++) {
        if (bias != nullptr) {
            const int c = tN + n_base + in * 8 + 2 * (lane & 3);
            b0[in] = __ldg(bias + c);
            b1[in] = __ldg(bias + c + 1);
        } else { b0[in] = 0.f; b1[in] = 0.f; }
    }
#pragma unroll
    for (int im = 0; im < 4; im++)
#pragma unroll
        for (int in = 0; in < 4; in++) {
            acc[im][in][0] += b0[in];
            acc[im][in][1] += b1[in];
            acc[im][in][2] += b0[in];
            acc[im][in][3] += b1[in];
        }

    if (FUSE_SM) {
        float* red = (float*)smraw;
        float* red2 = red + 512;
        const int wn = warp >> 1;

        float m0[4], m1[4];
#pragma unroll
        for (int im = 0; im < 4; im++) {
            float a = -1e30f, b = -1e30f;
#pragma unroll
            for (int in = 0; in < 4; in++) {
                a = fmaxf(a, fmaxf(acc[im][in][0], acc[im][in][1]));
                b = fmaxf(b, fmaxf(acc[im][in][2], acc[im][in][3]));
            }
            a = fmaxf(a, __shfl_xor_sync(0xffffffffu, a, 1));
            a = fmaxf(a, __shfl_xor_sync(0xffffffffu, a, 2));
            b = fmaxf(b, __shfl_xor_sync(0xffffffffu, b, 1));
            b = fmaxf(b, __shfl_xor_sync(0xffffffffu, b, 2));
            m0[im] = a; m1[im] = b;
        }
        if ((lane & 3) == 0) {
#pragma unroll
            for (int im = 0; im < 4; im++) {
                const int r = m_base + im * 16 + (lane >> 2);
                red[r * 4 + wn] = m0[im];
                red[(r + 8) * 4 + wn] = m1[im];
            }
        }
        __syncthreads();
        float M0[4], M1[4];
#pragma unroll
        for (int im = 0; im < 4; im++) {
            const int r = m_base + im * 16 + (lane >> 2);
            M0[im] = fmaxf(fmaxf(red[r * 4], red[r * 4 + 1]),
                           fmaxf(red[r * 4 + 2], red[r * 4 + 3]));
            M1[im] = fmaxf(fmaxf(red[(r + 8) * 4], red[(r + 8) * 4 + 1]),
                           fmaxf(red[(r + 8) * 4 + 2], red[(r + 8) * 4 + 3]));
        }
        float s0[4], s1[4];
#pragma unroll
        for (int im = 0; im < 4; im++) {
            float sa = 0.f, sb = 0.f;
#pragma unroll
            for (int in = 0; in < 4; in++) {
                acc[im][in][0] = __expf(acc[im][in][0] - M0[im]);
                acc[im][in][1] = __expf(acc[im][in][1] - M0[im]);
                acc[im][in][2] = __expf(acc[im][in][2] - M1[im]);
                acc[im][in][3] = __expf(acc[im][in][3] - M1[im]);
                sa += acc[im][in][0] + acc[im][in][1];
                sb += acc[im][in][2] + acc[im][in][3];
            }
            sa += __shfl_xor_sync(0xffffffffu, sa, 1);
            sa += __shfl_xor_sync(0xffffffffu, sa, 2);
            sb += __shfl_xor_sync(0xffffffffu, sb, 1);
            sb += __shfl_xor_sync(0xffffffffu, sb, 2);
            s0[im] = sa; s1[im] = sb;
        }
        if ((lane & 3) == 0) {
#pragma unroll
            for (int im = 0; im < 4; im++) {
                const int r = m_base + im * 16 + (lane >> 2);
                red2[r * 4 + wn] = s0[im];
                red2[(r + 8) * 4 + wn] = s1[im];
            }
        }
        __syncthreads();
#pragma unroll
        for (int im = 0; im < 4; im++) {
            const int r = m_base + im * 16 + (lane >> 2);
            const float inv0 = 1.f / (red2[r * 4] + red2[r * 4 + 1] +
                                      red2[r * 4 + 2] + red2[r * 4 + 3]);
            const float inv1 = 1.f / (red2[(r + 8) * 4] + red2[(r + 8) * 4 + 1] +
                                      red2[(r + 8) * 4 + 2] + red2[(r + 8) * 4 + 3]);
            const int r0 = tM + r;
#pragma unroll
            for (int in = 0; in < 4; in++) {
                const int c = tN + n_base + in * 8 + 2 * (lane & 3);
                *(half2*)((__half*)C + (size_t)r0 * ldc + c) =
                    __floats2half2_rn(acc[im][in][0] * inv0, acc[im][in][1] * inv0);
                *(half2*)((__half*)C + (size_t)(r0 + 8) * ldc + c) =
                    __floats2half2_rn(acc[im][in][2] * inv1, acc[im][in][3] * inv1);
            }
        }
    } else {
#pragma unroll
        for (int im = 0; im < 4; im++) {
            const int r0 = tM + m_base + im * 16 + (lane >> 2);
#pragma unroll
            for (int in = 0; in < 4; in++) {
                const int c = tN + n_base + in * 8 + 2 * (lane & 3);
                *(float2*)((float*)C + (size_t)r0 * ldc + c) =
                    make_float2(acc[im][in][0], acc[im][in][1]);
                *(float2*)((float*)C + (size_t)(r0 + 8) * ldc + c) =
                    make_float2(acc[im][in][2], acc[im][in][3]);
            }
        }
    }
}

// ---------------------------------------------------------------------------
// k column softmax stats (max, sumexp over N=512 per (b, d) column)
// ---------------------------------------------------------------------------
__global__ void kcol_stats(const float* __restrict__ k, float* __restrict__ om,
                           float* __restrict__ os) {
    const int b = blockIdx.x >> 5;
    const int cg = blockIdx.x & 31;
    const int cl = threadIdx.x & 31;
    const int seg = threadIdx.x >> 5;
    const int col = cg * 32 + cl;
    const float* p = k + (size_t)b * NN * DD + col;

    float m = -1e30f;
#pragma unroll 4
    for (int i = 0; i < 128; i++) m = fmaxf(m, p[(size_t)(seg * 128 + i) * DD]);

    __shared__ float smx[4][32], ssm[4][32], gmx[32];
    smx[seg][cl] = m;
    __syncthreads();
    if (seg == 0) {
        float M = fmaxf(fmaxf(smx[0][cl], smx[1][cl]), fmaxf(smx[2][cl], smx[3][cl]));
        gmx[cl] = M;
    }
    __syncthreads();
    const float M = gmx[cl];
    float s = 0.f;
#pragma unroll 4
    for (int i = 0; i < 128; i++) s += __expf(p[(size_t)(seg * 128 + i) * DD] - M);
    ssm[seg][cl] = s;
    __syncthreads();
    if (seg == 0) {
        float S = ssm[0][cl] + ssm[1][cl] + ssm[2][cl] + ssm[3][cl];
        om[b * DD + col] = M;
        os[b * DD + col] = S;
    }
}

// ---------------------------------------------------------------------------
// context partials: cp[split,bh,dk,dv] = (1/s_dk) * sum_n exp(k-m_dk) * v
// ---------------------------------------------------------------------------
__global__ void __launch_bounds__(256)
context_part(const float* __restrict__ k, const float* __restrict__ v,
             const float* __restrict__ km, const float* __restrict__ ks,
             float* __restrict__ cp) {
    const int bh = blockIdx.x;
    const int b = bh >> 3, h = bh & 7;
    const int split = blockIdx.y;
    __shared__ float Ks[32][132], Vs[32][132];

    const float* kb = k + (size_t)b * NN * DD + h * HD;
    const float* vb = v + (size_t)b * NN * DD + h * HD;
    const float* kmb = km + b * DD + h * HD;
    const float* ksb = ks + b * DD + h * HD;

    float acc[8][8];
#pragma unroll
    for (int i = 0; i < 8; i++)
#pragma unroll
        for (int j = 0; j < 8; j++) acc[i][j] = 0.f;

    const int tx = threadIdx.x & 15, ty = threadIdx.x >> 4;

    for (int c = 0; c < 4; c++) {
        const int n0 = split * 128 + c * 32;
        for (int t = threadIdx.x; t < 32 * 128; t += 256) {
            int nn = t >> 7, dd = t & 127;
            Ks[nn][dd] = __expf(kb[(size_t)(n0 + nn) * DD + dd] - kmb[dd]);
            Vs[nn][dd] = vb[(size_t)(n0 + nn) * DD + dd];
        }
        __syncthreads();
#pragma unroll 8
        for (int nn = 0; nn < 32; nn++) {
            float kr[8], vr[8];
#pragma unroll
            for (int i = 0; i < 8; i++) kr[i] = Ks[nn][ty * 8 + i];
#pragma unroll
            for (int j = 0; j < 8; j++) vr[j] = Vs[nn][tx * 8 + j];
#pragma unroll
            for (int i = 0; i < 8; i++)
#pragma unroll
                for (int j = 0; j < 8; j++) acc[i][j] += kr[i] * vr[j];
        }
        __syncthreads();
    }

    float* out = cp + ((size_t)split * 32 + bh) * (HD * HD);
#pragma unroll
    for (int i = 0; i < 8; i++) {
        const int dk = ty * 8 + i;
        const float rs = 1.f / ksb[dk];
#pragma unroll
        for (int j = 0; j < 8; j++)
            out[(size_t)dk * HD + tx * 8 + j] = acc[i][j] * rs;
    }
}

// sum 4 partials; fp16 output [bh][dk][dv] (B operand of y GEMM)
__global__ void ctx_reduce(const float* __restrict__ cp, __half* __restrict__ ctx) {
    const size_t i = (size_t)blockIdx.x * 256 + threadIdx.x;
    ctx[i] = __float2half_rn(cp[i] + cp[i + 524288] +
                             cp[i + 2 * 524288] + cp[i + 3 * 524288]);
}

// ---------------------------------------------------------------------------
// Launch
// ---------------------------------------------------------------------------
extern "C" void kernel_launch(void* const* d_in, const int* in_sizes, int n_in,
                              void* d_out, int out_size) {
    const float* x     = (const float*)d_in[0];
    const float* cond  = (const float*)d_in[1];
    const float* ln_g  = (const float*)d_in[2];
    const float* ln_b  = (const float*)d_in[3];
    const float* tln_g = (const float*)d_in[4];
    const float* tln_b = (const float*)d_in[5];
    const float* Wq    = (const float*)d_in[6];
    const float* bq    = (const float*)d_in[7];
    const float* Wk    = (const float*)d_in[8];
    const float* bk    = (const float*)d_in[9];
    const float* Wv    = (const float*)d_in[10];
    const float* bv    = (const float*)d_in[11];
    float* y = (float*)d_out;

    float* base = nullptr;
    cudaGetSymbolAddress((void**)&base, g_buf);
    __half* xn   = (__half*)(base + OFF_XN);
    __half* cn   = (__half*)(base + OFF_CN);
    __half* q    = (__half*)(base + OFF_Q);
    float*  kk   = base + OFF_K;
    float*  vv   = base + OFF_V;
    float*  km   = base + OFF_KM;
    float*  ks   = base + OFF_KS;
    float*  cp   = base + OFF_CP;
    __half* ctx  = (__half*)(base + OFF_CTX);
    __half* wq16 = (__half*)(base + OFF_WQ16);
    __half* wk16 = (__half*)(base + OFF_WK16);
    __half* wv16 = (__half*)(base + OFF_WV16);

    cudaFuncSetAttribute(gemm_fp16<true, __half>,
                         cudaFuncAttributeMaxDynamicSharedMemorySize, SMEM_BYTES);
    cudaFuncSetAttribute(gemm_fp16<false, float>,
                         cudaFuncAttributeMaxDynamicSharedMemorySize, SMEM_BYTES);

    // 0: convert weights to fp16 (layout [K, N] kept)
    conv_weights<<<2560, 256>>>(Wq, Wk, Wv, wq16);

    // 1-2: LayerNorms (fp16 outputs)
    ln_kernel<DD><<<BB * TT, 256>>>(x, ln_g, ln_b, xn);
    ln_kernel<LL><<<BB * NN, 256>>>(cond, tln_g, tln_b, cn);

    // 3: q = softmax_head(xn @ Wq + bq), fused softmax, fp16 output
    gemm_fp16<true, __half><<<dim3(DD / 128, (BB * TT) / 128, 1), 256, SMEM_BYTES>>>(
        xn, wq16, bq, q, nullptr, nullptr, nullptr,
        DD, DD, DD, DD, 1, 0, 0, 0, 0, 0);

    // 4: k,v = cn @ W{k,v} + b fused in one launch (f32 outputs)
    gemm_fp16<false, float><<<dim3(2 * DD / 128, (BB * NN) / 128, 1), 256, SMEM_BYTES>>>(
        cn, wk16, bk, kk, wv16, bv, vv,
        LL, LL, DD, DD, 1, 0, 0, 0, 0, 0);

    // 5: k column softmax stats (over N)
    kcol_stats<<<BB * (DD / 32), 128>>>(kk, km, ks);

    // 6-7: context = softmax_N(k)^T @ v  (4-way N split + fp16 reduce)
    context_part<<<dim3(BB * HH, 4), 256>>>(kk, vv, km, ks, cp);
    ctx_reduce<<<(BB * HH * HD * HD) / 256, 256>>>(cp, ctx);

    // 8: y = q_soft @ ctx, batched over (b,h), writes d_out (f32)
    gemm_fp16<false, float><<<dim3(1, TT / 128, BB * HH), 256, SMEM_BYTES>>>(
        q, ctx, nullptr, y, nullptr, nullptr, nullptr,
        HD, DD, HD, DD,
        HH, (long long)TT * DD, HD, (long long)HD * HD,
        (long long)TT * DD, HD);
}

// round 10
// speedup vs baseline: 1.7381x; 1.0605x over previous
#include <cuda_runtime.h>
#include <cuda_fp16.h>
#include <cstdint>

// ---------------------------------------------------------------------------
// Problem constants (fixed shapes from reference setup_inputs)
// ---------------------------------------------------------------------------
#define BB   4
#define TT   4096
#define NN   512
#define DD   1024
#define LL   768
#define HH   8
#define HD   128

// ---------------------------------------------------------------------------
// Scratch (single __device__ array; offsets in floats)
// ---------------------------------------------------------------------------
#define OFF_XN   0LL                                 // half [B*T,D]
#define OFF_CN   (OFF_XN + 8388608LL)                // half [B*N,L]
#define OFF_K    (OFF_CN + 786432LL)                 // f32  [B*N,D]
#define OFF_V    (OFF_K  + 2097152LL)                // f32  [B*N,D]
#define OFF_KM   (OFF_V  + 2097152LL)                // f32  [B,D]
#define OFF_KS   (OFF_KM + 4096LL)                   // f32  [B,D]
#define OFF_CP   (OFF_KS + 4096LL)                   // f32  [4,B*H,128,128]
#define OFF_CTX  (OFF_CP + 2097152LL)                // half [B*H,dk,dv]
#define OFF_WQ16 (OFF_CTX + 262144LL)                // half [1024,1024]
#define OFF_WK16 (OFF_WQ16 + 524288LL)               // half [768,1024]
#define OFF_WV16 (OFF_WK16 + 393216LL)               // half [768,1024]
#define SCRATCH_TOTAL (OFF_WV16 + 393216LL)

__device__ __align__(256) float g_buf[SCRATCH_TOTAL];

// ---------------------------------------------------------------------------
// Helpers
// ---------------------------------------------------------------------------
__device__ __forceinline__ void mma_fp16(float* c, const uint32_t* a, const uint32_t* b) {
    asm volatile(
        "mma.sync.aligned.m16n8k16.row.col.f32.f16.f16.f32 "
        "{%0,%1,%2,%3}, {%4,%5,%6,%7}, {%8,%9}, {%0,%1,%2,%3};\n"
        : "+f"(c[0]), "+f"(c[1]), "+f"(c[2]), "+f"(c[3])
        : "r"(a[0]), "r"(a[1]), "r"(a[2]), "r"(a[3]),
          "r"(b[0]), "r"(b[1]));
}

__device__ __forceinline__ void ldsm4(uint32_t& r0, uint32_t& r1, uint32_t& r2,
                                      uint32_t& r3, uint32_t addr) {
    asm volatile("ldmatrix.sync.aligned.m8n8.x4.shared.b16 {%0,%1,%2,%3}, [%4];\n"
                 : "=r"(r0), "=r"(r1), "=r"(r2), "=r"(r3) : "r"(addr));
}

__device__ __forceinline__ void ldsm4t(uint32_t& r0, uint32_t& r1, uint32_t& r2,
                                       uint32_t& r3, uint32_t addr) {
    asm volatile("ldmatrix.sync.aligned.m8n8.x4.trans.shared.b16 {%0,%1,%2,%3}, [%4];\n"
                 : "=r"(r0), "=r"(r1), "=r"(r2), "=r"(r3) : "r"(addr));
}

__device__ __forceinline__ void cp16(void* s, const void* g) {
    uint32_t sa = (uint32_t)__cvta_generic_to_shared(s);
    asm volatile("cp.async.cg.shared.global [%0], [%1], 16;\n" :: "r"(sa), "l"(g));
}

// ---------------------------------------------------------------------------
// Convert weights f32 -> f16 (layout kept [K, N])
// ---------------------------------------------------------------------------
__global__ void conv_weights(const float* __restrict__ wq, const float* __restrict__ wk,
                             const float* __restrict__ wv, __half* __restrict__ out) {
    const size_t fi = ((size_t)blockIdx.x * 256 + threadIdx.x) * 4;
    const float* src;
    size_t off;
    if (fi < 1048576) { src = wq; off = fi; }
    else if (fi < 1048576 + 786432) { src = wk; off = fi - 1048576; }
    else { src = wv; off = fi - (1048576 + 786432); }
    float4 v = *(const float4*)(src + off);
    *(half2*)(out + fi) = __floats2half2_rn(v.x, v.y);
    *(half2*)(out + fi + 2) = __floats2half2_rn(v.z, v.w);
}

// ---------------------------------------------------------------------------
// LayerNorm: one block per row, fp16 output (GEMM operand)
// ---------------------------------------------------------------------------
template <int DIM>
__global__ void ln_kernel(const float* __restrict__ x, const float* __restrict__ g,
                          const float* __restrict__ bta, __half* __restrict__ out) {
    constexpr int PER = DIM / 256;
    const size_t row = blockIdx.x;
    const float* xr = x + row * DIM;
    float v[PER];
    float s = 0.f, sq = 0.f;
#pragma unroll
    for (int i = 0; i < PER; i++) {
        v[i] = xr[threadIdx.x + 256 * i];
        s += v[i];
        sq += v[i] * v[i];
    }
#pragma unroll
    for (int o = 16; o; o >>= 1) {
        s += __shfl_xor_sync(0xffffffffu, s, o);
        sq += __shfl_xor_sync(0xffffffffu, sq, o);
    }
    __shared__ float sm[8], sv[8];
    int w = threadIdx.x >> 5;
    if ((threadIdx.x & 31) == 0) { sm[w] = s; sv[w] = sq; }
    __syncthreads();
    if (threadIdx.x < 32) {
        s = (threadIdx.x < 8) ? sm[threadIdx.x] : 0.f;
        sq = (threadIdx.x < 8) ? sv[threadIdx.x] : 0.f;
#pragma unroll
        for (int o = 4; o; o >>= 1) {
            s += __shfl_xor_sync(0xffffffffu, s, o);
            sq += __shfl_xor_sync(0xffffffffu, sq, o);
        }
        if (threadIdx.x == 0) { sm[0] = s; sv[0] = sq; }
    }
    __syncthreads();
    const float mean = sm[0] * (1.f / DIM);
    const float var = sv[0] * (1.f / DIM) - mean * mean;
    const float rstd = rsqrtf(var + 1e-5f);
    __half* orow = out + row * DIM;
#pragma unroll
    for (int i = 0; i < PER; i++) {
        int c = threadIdx.x + 256 * i;
        orow[c] = __float2half_rn((v[i] - mean) * rstd * g[c] + bta[c]);
    }
}

// ---------------------------------------------------------------------------
// fp16 tensor-core GEMM: 128x128 tile, BK=64, cp.async 3-stage, f32 accum.
// 8 warps (2m x 4n), warp tile 64x32.
// FUSE_PV: tile == one (b,head): row softmax -> P(fp16, smem) -> P @ ctx
//          (ctx cp.async'd during softmax) -> y (f32) written directly.
// Dual (Bm2!=null): grid.x split between {Bm,bias,C} and {Bm2,bias2,C2}.
// ---------------------------------------------------------------------------
#define STAGES 3
#define AS_H 72              // halves per A smem row (64 + 8 pad)
#define BS_H 136             // halves per B smem row (128 + 8 pad)
#define A_ST_H (128 * AS_H)
#define B_ST_H (64 * BS_H)
#define SMEM_BYTES (STAGES * (A_ST_H + B_ST_H) * 2)   // 107520
// FUSE epilogue smem plan (inside the 107520 bytes, reused post-mainloop):
#define P_OFF   8192
#define CTX_OFF (P_OFF + 128 * BS_H * 2)              // 8192 + 34816 = 43008
#define RED_OFF (CTX_OFF + 128 * BS_H * 2)            // 77824 (+4KB <= 107520)

template <bool FUSE_PV, typename OutT>
__global__ void __launch_bounds__(256, 2)
gemm_fp16(const __half* __restrict__ A, const __half* __restrict__ Bm,
          const float* __restrict__ bias, OutT* __restrict__ C,
          const __half* __restrict__ Bm2, const float* __restrict__ bias2,
          OutT* __restrict__ C2, const __half* __restrict__ ctxg,
          int K, int lda, int ldb, int ldc) {
    extern __shared__ __align__(16) char smraw[];
    __half* Asm = (__half*)smraw;
    __half* Bsm = Asm + STAGES * A_ST_H;

    int tN;
    if (Bm2 != nullptr) {
        const int half_g = gridDim.x >> 1;
        if (blockIdx.x >= half_g) {
            Bm = Bm2; bias = bias2; C = C2;
            tN = (blockIdx.x - half_g) * 128;
        } else {
            tN = blockIdx.x * 128;
        }
    } else {
        tN = blockIdx.x * 128;
    }
    const int tM = blockIdx.y * 128;
    const int tid = threadIdx.x;
    const int lane = tid & 31, warp = tid >> 5;
    const int m_base = (warp & 1) * 64;
    const int n_base = (warp >> 1) * 32;

    const __half* Ag = A + (size_t)tM * lda;
    const __half* Bg = Bm + tN;
    const int nk = K >> 6;   // BK = 64

    auto issue = [&](int kt) {
        const int st = kt % STAGES;
        __half* Al = Asm + st * A_ST_H;
        __half* Bl = Bsm + st * B_ST_H;
        const int k0 = kt << 6;
#pragma unroll
        for (int j = 0; j < 4; j++) {
            const int ci = tid + 256 * j;
            const int r = ci >> 3, c = (ci & 7) * 8;
            cp16(Al + r * AS_H + c, Ag + (size_t)r * lda + k0 + c);
        }
#pragma unroll
        for (int j = 0; j < 4; j++) {
            const int ci = tid + 256 * j;
            const int r = ci >> 4, c = (ci & 15) * 8;
            cp16(Bl + r * BS_H + c, Bg + (size_t)(k0 + r) * ldb + c);
        }
    };

    const uint32_t asm_u32 = (uint32_t)__cvta_generic_to_shared(Asm);
    const uint32_t bsm_u32 = (uint32_t)__cvta_generic_to_shared(Bsm);
    const uint32_t a_lane = (uint32_t)(((lane & 15) * AS_H + (lane >> 4) * 8) * 2);
    const uint32_t b_lane = (uint32_t)(((lane & 15) * BS_H + (lane >> 4) * 8) * 2);

    float acc[4][4][4];
#pragma unroll
    for (int i = 0; i < 4; i++)
#pragma unroll
        for (int j = 0; j < 4; j++)
#pragma unroll
            for (int r = 0; r < 4; r++) acc[i][j][r] = 0.f;

    issue(0);
    asm volatile("cp.async.commit_group;\n");
    issue(1);
    asm volatile("cp.async.commit_group;\n");

    for (int kt = 0; kt < nk; kt++) {
        asm volatile("cp.async.wait_group %0;\n" :: "n"(1));
        __syncthreads();
        if (kt + 2 < nk) issue(kt + 2);
        asm volatile("cp.async.commit_group;\n");

        const int st = kt % STAGES;
        const uint32_t a_st = asm_u32 + (uint32_t)(st * A_ST_H * 2) + a_lane;
        const uint32_t b_st = bsm_u32 + (uint32_t)(st * B_ST_H * 2) + b_lane;
#pragma unroll
        for (int kk = 0; kk < 4; kk++) {
            uint32_t af[4][4];
#pragma unroll
            for (int im = 0; im < 4; im++)
                ldsm4(af[im][0], af[im][1], af[im][2], af[im][3],
                      a_st + (uint32_t)(((m_base + im * 16) * AS_H + kk * 16) * 2));
            uint32_t bf[2][4];
#pragma unroll
            for (int t = 0; t < 2; t++)
                ldsm4t(bf[t][0], bf[t][1], bf[t][2], bf[t][3],
                       b_st + (uint32_t)((kk * 16 * BS_H + n_base + t * 16) * 2));
#pragma unroll
            for (int im = 0; im < 4; im++)
#pragma unroll
                for (int in = 0; in < 4; in++)
                    mma_fp16(acc[im][in], af[im], &bf[in >> 1][(in & 1) * 2]);
        }
    }
    __syncthreads();   // mainloop smem dead; epilogue may reuse

    // -------- bias --------
    float b0[4], b1[4];
#pragma unroll
    for (int in = 0; in < 4; in++) {
        if (bias != nullptr) {
            const int c = tN + n_base + in * 8 + 2 * (lane & 3);
            b0[in] = __ldg(bias + c);
            b1[in] = __ldg(bias + c + 1);
        } else { b0[in] = 0.f; b1[in] = 0.f; }
    }
#pragma unroll
    for (int im = 0; im < 4; im++)
#pragma unroll
        for (int in = 0; in < 4; in++) {
            acc[im][in][0] += b0[in];
            acc[im][in][1] += b1[in];
            acc[im][in][2] += b0[in];
            acc[im][in][3] += b1[in];
        }

    if (FUSE_PV) {
        // ---- start ctx loads (overlap with softmax math) ----
        __half* Psm = (__half*)(smraw + P_OFF);
        __half* Csm = (__half*)(smraw + CTX_OFF);
        float* red = (float*)(smraw + RED_OFF);
        float* red2 = red + 512;
        const int bh = (tM >> 12) * HH + blockIdx.x;   // b = tM/T, h = blockIdx.x
        const __half* cg = ctxg + ((size_t)bh << 14);
#pragma unroll
        for (int j = 0; j < 8; j++) {                   // 128 rows x 128 halves
            const int ci = tid + 256 * j;
            const int r = ci >> 4, c = (ci & 15) * 8;
            cp16(Csm + r * BS_H + c, cg + (size_t)r * HD + c);
        }
        asm volatile("cp.async.commit_group;\n");

        // ---- row softmax over 128 cols (4 n-warp groups via smem) ----
        const int wn = warp >> 1;
        float m0[4], m1[4];
#pragma unroll
        for (int im = 0; im < 4; im++) {
            float a = -1e30f, b = -1e30f;
#pragma unroll
            for (int in = 0; in < 4; in++) {
                a = fmaxf(a, fmaxf(acc[im][in][0], acc[im][in][1]));
                b = fmaxf(b, fmaxf(acc[im][in][2], acc[im][in][3]));
            }
            a = fmaxf(a, __shfl_xor_sync(0xffffffffu, a, 1));
            a = fmaxf(a, __shfl_xor_sync(0xffffffffu, a, 2));
            b = fmaxf(b, __shfl_xor_sync(0xffffffffu, b, 1));
            b = fmaxf(b, __shfl_xor_sync(0xffffffffu, b, 2));
            m0[im] = a; m1[im] = b;
        }
        if ((lane & 3) == 0) {
#pragma unroll
            for (int im = 0; im < 4; im++) {
                const int r = m_base + im * 16 + (lane >> 2);
                red[r * 4 + wn] = m0[im];
                red[(r + 8) * 4 + wn] = m1[im];
            }
        }
        __syncthreads();
        float M0[4], M1[4];
#pragma unroll
        for (int im = 0; im < 4; im++) {
            const int r = m_base + im * 16 + (lane >> 2);
            M0[im] = fmaxf(fmaxf(red[r * 4], red[r * 4 + 1]),
                           fmaxf(red[r * 4 + 2], red[r * 4 + 3]));
            M1[im] = fmaxf(fmaxf(red[(r + 8) * 4], red[(r + 8) * 4 + 1]),
                           fmaxf(red[(r + 8) * 4 + 2], red[(r + 8) * 4 + 3]));
        }
        float s0[4], s1[4];
#pragma unroll
        for (int im = 0; im < 4; im++) {
            float sa = 0.f, sb = 0.f;
#pragma unroll
            for (int in = 0; in < 4; in++) {
                acc[im][in][0] = __expf(acc[im][in][0] - M0[im]);
                acc[im][in][1] = __expf(acc[im][in][1] - M0[im]);
                acc[im][in][2] = __expf(acc[im][in][2] - M1[im]);
                acc[im][in][3] = __expf(acc[im][in][3] - M1[im]);
                sa += acc[im][in][0] + acc[im][in][1];
                sb += acc[im][in][2] + acc[im][in][3];
            }
            sa += __shfl_xor_sync(0xffffffffu, sa, 1);
            sa += __shfl_xor_sync(0xffffffffu, sa, 2);
            sb += __shfl_xor_sync(0xffffffffu, sb, 1);
            sb += __shfl_xor_sync(0xffffffffu, sb, 2);
            s0[im] = sa; s1[im] = sb;
        }
        if ((lane & 3) == 0) {
#pragma unroll
            for (int im = 0; im < 4; im++) {
                const int r = m_base + im * 16 + (lane >> 2);
                red2[r * 4 + wn] = s0[im];
                red2[(r + 8) * 4 + wn] = s1[im];
            }
        }
        __syncthreads();
        // ---- P (fp16) to smem ----
#pragma unroll
        for (int im = 0; im < 4; im++) {
            const int r = m_base + im * 16 + (lane >> 2);
            const float inv0 = 1.f / (red2[r * 4] + red2[r * 4 + 1] +
                                      red2[r * 4 + 2] + red2[r * 4 + 3]);
            const float inv1 = 1.f / (red2[(r + 8) * 4] + red2[(r + 8) * 4 + 1] +
                                      red2[(r + 8) * 4 + 2] + red2[(r + 8) * 4 + 3]);
#pragma unroll
            for (int in = 0; in < 4; in++) {
                const int c = n_base + in * 8 + 2 * (lane & 3);
                *(half2*)(Psm + (size_t)r * BS_H + c) =
                    __floats2half2_rn(acc[im][in][0] * inv0, acc[im][in][1] * inv0);
                *(half2*)(Psm + (size_t)(r + 8) * BS_H + c) =
                    __floats2half2_rn(acc[im][in][2] * inv1, acc[im][in][3] * inv1);
            }
        }
        asm volatile("cp.async.wait_group 0;\n");
        __syncthreads();

        // ---- second GEMM: y[128,128] = P @ ctx ----
        float ac2[4][4][4];
#pragma unroll
        for (int i = 0; i < 4; i++)
#pragma unroll
            for (int j = 0; j < 4; j++)
#pragma unroll
                for (int r = 0; r < 4; r++) ac2[i][j][r] = 0.f;

        const uint32_t p_u32 = (uint32_t)__cvta_generic_to_shared(Psm) + b_lane;
        const uint32_t c_u32 = (uint32_t)__cvta_generic_to_shared(Csm) + b_lane;
#pragma unroll
        for (int kk = 0; kk < 8; kk++) {
            uint32_t af[4][4];
#pragma unroll
            for (int im = 0; im < 4; im++)
                ldsm4(af[im][0], af[im][1], af[im][2], af[im][3],
                      p_u32 + (uint32_t)(((m_base + im * 16) * BS_H + kk * 16) * 2));
            uint32_t bf[2][4];
#pragma unroll
            for (int t = 0; t < 2; t++)
                ldsm4t(bf[t][0], bf[t][1], bf[t][2], bf[t][3],
                       c_u32 + (uint32_t)((kk * 16 * BS_H + n_base + t * 16) * 2));
#pragma unroll
            for (int im = 0; im < 4; im++)
#pragma unroll
                for (int in = 0; in < 4; in++)
                    mma_fp16(ac2[im][in], af[im], &bf[in >> 1][(in & 1) * 2]);
        }
        // y write (f32) — tile cols = head blockIdx.x
#pragma unroll
        for (int im = 0; im < 4; im++) {
            const int r0 = tM + m_base + im * 16 + (lane >> 2);
#pragma unroll
            for (int in = 0; in < 4; in++) {
                const int c = tN + n_base + in * 8 + 2 * (lane & 3);
                *(float2*)((float*)C + (size_t)r0 * ldc + c) =
                    make_float2(ac2[im][in][0], ac2[im][in][1]);
                *(float2*)((float*)C + (size_t)(r0 + 8) * ldc + c) =
                    make_float2(ac2[im][in][2], ac2[im][in][3]);
            }
        }
    } else {
#pragma unroll
        for (int im = 0; im < 4; im++) {
            const int r0 = tM + m_base + im * 16 + (lane >> 2);
#pragma unroll
            for (int in = 0; in < 4; in++) {
                const int c = tN + n_base + in * 8 + 2 * (lane & 3);
                *(float2*)((float*)C + (size_t)r0 * ldc + c) =
                    make_float2(acc[im][in][0], acc[im][in][1]);
                *(float2*)((float*)C + (size_t)(r0 + 8) * ldc + c) =
                    make_float2(acc[im][in][2], acc[im][in][3]);
            }
        }
    }
}

// ---------------------------------------------------------------------------
// k column softmax stats (max, sumexp over N=512 per (b, d) column)
// ---------------------------------------------------------------------------
__global__ void kcol_stats(const float* __restrict__ k, float* __restrict__ om,
                           float* __restrict__ os) {
    const int b = blockIdx.x >> 5;
    const int cg = blockIdx.x & 31;
    const int cl = threadIdx.x & 31;
    const int seg = threadIdx.x >> 5;
    const int col = cg * 32 + cl;
    const float* p = k + (size_t)b * NN * DD + col;

    float m = -1e30f;
#pragma unroll 4
    for (int i = 0; i < 128; i++) m = fmaxf(m, p[(size_t)(seg * 128 + i) * DD]);

    __shared__ float smx[4][32], ssm[4][32], gmx[32];
    smx[seg][cl] = m;
    __syncthreads();
    if (seg == 0) {
        float M = fmaxf(fmaxf(smx[0][cl], smx[1][cl]), fmaxf(smx[2][cl], smx[3][cl]));
        gmx[cl] = M;
    }
    __syncthreads();
    const float M = gmx[cl];
    float s = 0.f;
#pragma unroll 4
    for (int i = 0; i < 128; i++) s += __expf(p[(size_t)(seg * 128 + i) * DD] - M);
    ssm[seg][cl] = s;
    __syncthreads();
    if (seg == 0) {
        float S = ssm[0][cl] + ssm[1][cl] + ssm[2][cl] + ssm[3][cl];
        om[b * DD + col] = M;
        os[b * DD + col] = S;
    }
}

// ---------------------------------------------------------------------------
// context partials: cp[split,bh,dk,dv] = (1/s_dk) * sum_n exp(k-m_dk) * v
// ---------------------------------------------------------------------------
__global__ void __launch_bounds__(256)
context_part(const float* __restrict__ k, const float* __restrict__ v,
             const float* __restrict__ km, const float* __restrict__ ks,
             float* __restrict__ cp) {
    const int bh = blockIdx.x;
    const int b = bh >> 3, h = bh & 7;
    const int split = blockIdx.y;
    __shared__ float Ks[32][132], Vs[32][132];

    const float* kb = k + (size_t)b * NN * DD + h * HD;
    const float* vb = v + (size_t)b * NN * DD + h * HD;
    const float* kmb = km + b * DD + h * HD;
    const float* ksb = ks + b * DD + h * HD;

    float acc[8][8];
#pragma unroll
    for (int i = 0; i < 8; i++)
#pragma unroll
        for (int j = 0; j < 8; j++) acc[i][j] = 0.f;

    const int tx = threadIdx.x & 15, ty = threadIdx.x >> 4;

    for (int c = 0; c < 4; c++) {
        const int n0 = split * 128 + c * 32;
        for (int t = threadIdx.x; t < 32 * 128; t += 256) {
            int nn = t >> 7, dd = t & 127;
            Ks[nn][dd] = __expf(kb[(size_t)(n0 + nn) * DD + dd] - kmb[dd]);
            Vs[nn][dd] = vb[(size_t)(n0 + nn) * DD + dd];
        }
        __syncthreads();
#pragma unroll 8
        for (int nn = 0; nn < 32; nn++) {
            float kr[8], vr[8];
#pragma unroll
            for (int i = 0; i < 8; i++) kr[i] = Ks[nn][ty * 8 + i];
#pragma unroll
            for (int j = 0; j < 8; j++) vr[j] = Vs[nn][tx * 8 + j];
#pragma unroll
            for (int i = 0; i < 8; i++)
#pragma unroll
                for (int j = 0; j < 8; j++) acc[i][j] += kr[i] * vr[j];
        }
        __syncthreads();
    }

    float* out = cp + ((size_t)split * 32 + bh) * (HD * HD);
#pragma unroll
    for (int i = 0; i < 8; i++) {
        const int dk = ty * 8 + i;
        const float rs = 1.f / ksb[dk];
#pragma unroll
        for (int j = 0; j < 8; j++)
            out[(size_t)dk * HD + tx * 8 + j] = acc[i][j] * rs;
    }
}

// sum 4 partials; fp16 output [bh][dk][dv] (B operand of fused PV)
__global__ void ctx_reduce(const float* __restrict__ cp, __half* __restrict__ ctx) {
    const size_t i = (size_t)blockIdx.x * 256 + threadIdx.x;
    ctx[i] = __float2half_rn(cp[i] + cp[i + 524288] +
                             cp[i + 2 * 524288] + cp[i + 3 * 524288]);
}

// ---------------------------------------------------------------------------
// Launch
// ---------------------------------------------------------------------------
extern "C" void kernel_launch(void* const* d_in, const int* in_sizes, int n_in,
                              void* d_out, int out_size) {
    const float* x     = (const float*)d_in[0];
    const float* cond  = (const float*)d_in[1];
    const float* ln_g  = (const float*)d_in[2];
    const float* ln_b  = (const float*)d_in[3];
    const float* tln_g = (const float*)d_in[4];
    const float* tln_b = (const float*)d_in[5];
    const float* Wq    = (const float*)d_in[6];
    const float* bq    = (const float*)d_in[7];
    const float* Wk    = (const float*)d_in[8];
    const float* bk    = (const float*)d_in[9];
    const float* Wv    = (const float*)d_in[10];
    const float* bv    = (const float*)d_in[11];
    float* y = (float*)d_out;

    float* base = nullptr;
    cudaGetSymbolAddress((void**)&base, g_buf);
    __half* xn   = (__half*)(base + OFF_XN);
    __half* cn   = (__half*)(base + OFF_CN);
    float*  kk   = base + OFF_K;
    float*  vv   = base + OFF_V;
    float*  km   = base + OFF_KM;
    float*  ks   = base + OFF_KS;
    float*  cp   = base + OFF_CP;
    __half* ctx  = (__half*)(base + OFF_CTX);
    __half* wq16 = (__half*)(base + OFF_WQ16);
    __half* wk16 = (__half*)(base + OFF_WK16);
    __half* wv16 = (__half*)(base + OFF_WV16);

    cudaFuncSetAttribute(gemm_fp16<true, float>,
                         cudaFuncAttributeMaxDynamicSharedMemorySize, SMEM_BYTES);
    cudaFuncSetAttribute(gemm_fp16<false, float>,
                         cudaFuncAttributeMaxDynamicSharedMemorySize, SMEM_BYTES);

    // 0: convert weights to fp16; LN(cond)
    conv_weights<<<2560, 256>>>(Wq, Wk, Wv, wq16);
    ln_kernel<LL><<<BB * NN, 256>>>(cond, tln_g, tln_b, cn);

    // 1: k,v = cn @ W{k,v} + b fused in one launch (f32 outputs)
    gemm_fp16<false, float><<<dim3(2 * DD / 128, (BB * NN) / 128, 1), 256, SMEM_BYTES>>>(
        cn, wk16, bk, kk, wv16, bv, vv, nullptr,
        LL, LL, DD, DD);

    // 2: k column softmax stats (over N)
    kcol_stats<<<BB * (DD / 32), 128>>>(kk, km, ks);

    // 3-4: context = softmax_N(k)^T @ v  (4-way N split + fp16 reduce)
    context_part<<<dim3(BB * HH, 4), 256>>>(kk, vv, km, ks, cp);
    ctx_reduce<<<(BB * HH * HD * HD) / 256, 256>>>(cp, ctx);

    // 5: LN(x) (fp16 output) — just before the fused kernel
    ln_kernel<DD><<<BB * TT, 256>>>(x, ln_g, ln_b, xn);

    // 6: FUSED: q = softmax_head(xn @ Wq + bq); y = q @ ctx  -> d_out (f32)
    gemm_fp16<true, float><<<dim3(DD / 128, (BB * TT) / 128, 1), 256, SMEM_BYTES>>>(
        xn, wq16, bq, y, nullptr, nullptr, nullptr, ctx,
        DD, DD, DD, DD);
}

// round 11
// speedup vs baseline: 1.9591x; 1.1272x over previous
#include <cuda_runtime.h>
#include <cuda_fp16.h>
#include <cstdint>

// ---------------------------------------------------------------------------
// Problem constants (fixed shapes from reference setup_inputs)
// ---------------------------------------------------------------------------
#define BB   4
#define TT   4096
#define NN   512
#define DD   1024
#define LL   768
#define HH   8
#define HD   128

// ---------------------------------------------------------------------------
// Scratch (single __device__ array; offsets in floats)
// ---------------------------------------------------------------------------
#define NSPLIT 8
#define OFF_XN   0LL                                 // half [B*T,D]
#define OFF_CN   (OFF_XN + 8388608LL)                // half [B*N,L]
#define OFF_K    (OFF_CN + 786432LL)                 // f32  [B*N,D]
#define OFF_V    (OFF_K  + 2097152LL)                // f32  [B*N,D]
#define OFF_KM   (OFF_V  + 2097152LL)                // f32  [B,D]
#define OFF_KS   (OFF_KM + 4096LL)                   // f32  [B,D]
#define OFF_CP   (OFF_KS + 4096LL)                   // f32  [NSPLIT,B*H,128,128]
#define OFF_CTX  (OFF_CP + 4194304LL)                // half [B*H,dk,dv]
#define OFF_WQ16 (OFF_CTX + 262144LL)                // half [1024,1024]
#define OFF_WK16 (OFF_WQ16 + 524288LL)               // half [768,1024]
#define OFF_WV16 (OFF_WK16 + 393216LL)               // half [768,1024]
#define SCRATCH_TOTAL (OFF_WV16 + 393216LL)

__device__ __align__(256) float g_buf[SCRATCH_TOTAL];

// ---------------------------------------------------------------------------
// Helpers
// ---------------------------------------------------------------------------
__device__ __forceinline__ void mma_fp16(float* c, const uint32_t* a, const uint32_t* b) {
    asm volatile(
        "mma.sync.aligned.m16n8k16.row.col.f32.f16.f16.f32 "
        "{%0,%1,%2,%3}, {%4,%5,%6,%7}, {%8,%9}, {%0,%1,%2,%3};\n"
        : "+f"(c[0]), "+f"(c[1]), "+f"(c[2]), "+f"(c[3])
        : "r"(a[0]), "r"(a[1]), "r"(a[2]), "r"(a[3]),
          "r"(b[0]), "r"(b[1]));
}

__device__ __forceinline__ void ldsm4(uint32_t& r0, uint32_t& r1, uint32_t& r2,
                                      uint32_t& r3, uint32_t addr) {
    asm volatile("ldmatrix.sync.aligned.m8n8.x4.shared.b16 {%0,%1,%2,%3}, [%4];\n"
                 : "=r"(r0), "=r"(r1), "=r"(r2), "=r"(r3) : "r"(addr));
}

__device__ __forceinline__ void ldsm4t(uint32_t& r0, uint32_t& r1, uint32_t& r2,
                                       uint32_t& r3, uint32_t addr) {
    asm volatile("ldmatrix.sync.aligned.m8n8.x4.trans.shared.b16 {%0,%1,%2,%3}, [%4];\n"
                 : "=r"(r0), "=r"(r1), "=r"(r2), "=r"(r3) : "r"(addr));
}

__device__ __forceinline__ void cp16(void* s, const void* g) {
    uint32_t sa = (uint32_t)__cvta_generic_to_shared(s);
    asm volatile("cp.async.cg.shared.global [%0], [%1], 16;\n" :: "r"(sa), "l"(g));
}

// ---------------------------------------------------------------------------
// Convert weights f32 -> f16 (layout kept [K, N])
// ---------------------------------------------------------------------------
__global__ void conv_weights(const float* __restrict__ wq, const float* __restrict__ wk,
                             const float* __restrict__ wv, __half* __restrict__ out) {
    const size_t fi = ((size_t)blockIdx.x * 256 + threadIdx.x) * 4;
    const float* src;
    size_t off;
    if (fi < 1048576) { src = wq; off = fi; }
    else if (fi < 1048576 + 786432) { src = wk; off = fi - 1048576; }
    else { src = wv; off = fi - (1048576 + 786432); }
    float4 v = *(const float4*)(src + off);
    *(half2*)(out + fi) = __floats2half2_rn(v.x, v.y);
    *(half2*)(out + fi + 2) = __floats2half2_rn(v.z, v.w);
}

// ---------------------------------------------------------------------------
// LayerNorm: one block per row, fp16 output (GEMM operand)
// ---------------------------------------------------------------------------
template <int DIM>
__global__ void ln_kernel(const float* __restrict__ x, const float* __restrict__ g,
                          const float* __restrict__ bta, __half* __restrict__ out) {
    constexpr int PER = DIM / 256;
    const size_t row = blockIdx.x;
    const float* xr = x + row * DIM;
    float v[PER];
    float s = 0.f, sq = 0.f;
#pragma unroll
    for (int i = 0; i < PER; i++) {
        v[i] = xr[threadIdx.x + 256 * i];
        s += v[i];
        sq += v[i] * v[i];
    }
#pragma unroll
    for (int o = 16; o; o >>= 1) {
        s += __shfl_xor_sync(0xffffffffu, s, o);
        sq += __shfl_xor_sync(0xffffffffu, sq, o);
    }
    __shared__ float sm[8], sv[8];
    int w = threadIdx.x >> 5;
    if ((threadIdx.x & 31) == 0) { sm[w] = s; sv[w] = sq; }
    __syncthreads();
    if (threadIdx.x < 32) {
        s = (threadIdx.x < 8) ? sm[threadIdx.x] : 0.f;
        sq = (threadIdx.x < 8) ? sv[threadIdx.x] : 0.f;
#pragma unroll
        for (int o = 4; o; o >>= 1) {
            s += __shfl_xor_sync(0xffffffffu, s, o);
            sq += __shfl_xor_sync(0xffffffffu, sq, o);
        }
        if (threadIdx.x == 0) { sm[0] = s; sv[0] = sq; }
    }
    __syncthreads();
    const float mean = sm[0] * (1.f / DIM);
    const float var = sv[0] * (1.f / DIM) - mean * mean;
    const float rstd = rsqrtf(var + 1e-5f);
    __half* orow = out + row * DIM;
#pragma unroll
    for (int i = 0; i < PER; i++) {
        int c = threadIdx.x + 256 * i;
        orow[c] = __float2half_rn((v[i] - mean) * rstd * g[c] + bta[c]);
    }
}

// ---------------------------------------------------------------------------
// fp16 tensor-core GEMM: 128x128 tile, BK=64, cp.async 3-stage, f32 accum.
// 8 warps (2m x 4n), warp tile 64x32.
// FUSE_PV: tile == one (b,head): row softmax -> P(fp16, smem) -> P @ ctx
//          (ctx cp.async'd during softmax) -> y (f32) written directly.
// Dual (Bm2!=null): grid.x split between {Bm,bias,C} and {Bm2,bias2,C2}.
// ---------------------------------------------------------------------------
#define STAGES 3
#define AS_H 72              // halves per A smem row (64 + 8 pad)
#define BS_H 136             // halves per B smem row (128 + 8 pad)
#define A_ST_H (128 * AS_H)
#define B_ST_H (64 * BS_H)
#define SMEM_BYTES (STAGES * (A_ST_H + B_ST_H) * 2)   // 107520
// FUSE epilogue smem plan (inside the 107520 bytes, reused post-mainloop):
#define P_OFF   8192
#define CTX_OFF (P_OFF + 128 * BS_H * 2)              // 43008
#define RED_OFF (CTX_OFF + 128 * BS_H * 2)            // 77824 (+4KB <= 107520)

template <bool FUSE_PV, typename OutT>
__global__ void __launch_bounds__(256, 2)
gemm_fp16(const __half* __restrict__ A, const __half* __restrict__ Bm,
          const float* __restrict__ bias, OutT* __restrict__ C,
          const __half* __restrict__ Bm2, const float* __restrict__ bias2,
          OutT* __restrict__ C2, const __half* __restrict__ ctxg,
          int K, int lda, int ldb, int ldc) {
    extern __shared__ __align__(16) char smraw[];
    __half* Asm = (__half*)smraw;
    __half* Bsm = Asm + STAGES * A_ST_H;

    int tN;
    if (Bm2 != nullptr) {
        const int half_g = gridDim.x >> 1;
        if (blockIdx.x >= half_g) {
            Bm = Bm2; bias = bias2; C = C2;
            tN = (blockIdx.x - half_g) * 128;
        } else {
            tN = blockIdx.x * 128;
        }
    } else {
        tN = blockIdx.x * 128;
    }
    const int tM = blockIdx.y * 128;
    const int tid = threadIdx.x;
    const int lane = tid & 31, warp = tid >> 5;
    const int m_base = (warp & 1) * 64;
    const int n_base = (warp >> 1) * 32;

    const __half* Ag = A + (size_t)tM * lda;
    const __half* Bg = Bm + tN;
    const int nk = K >> 6;   // BK = 64

    auto issue = [&](int kt) {
        const int st = kt % STAGES;
        __half* Al = Asm + st * A_ST_H;
        __half* Bl = Bsm + st * B_ST_H;
        const int k0 = kt << 6;
#pragma unroll
        for (int j = 0; j < 4; j++) {
            const int ci = tid + 256 * j;
            const int r = ci >> 3, c = (ci & 7) * 8;
            cp16(Al + r * AS_H + c, Ag + (size_t)r * lda + k0 + c);
        }
#pragma unroll
        for (int j = 0; j < 4; j++) {
            const int ci = tid + 256 * j;
            const int r = ci >> 4, c = (ci & 15) * 8;
            cp16(Bl + r * BS_H + c, Bg + (size_t)(k0 + r) * ldb + c);
        }
    };

    const uint32_t asm_u32 = (uint32_t)__cvta_generic_to_shared(Asm);
    const uint32_t bsm_u32 = (uint32_t)__cvta_generic_to_shared(Bsm);
    const uint32_t a_lane = (uint32_t)(((lane & 15) * AS_H + (lane >> 4) * 8) * 2);
    const uint32_t b_lane = (uint32_t)(((lane & 15) * BS_H + (lane >> 4) * 8) * 2);

    float acc[4][4][4];
#pragma unroll
    for (int i = 0; i < 4; i++)
#pragma unroll
        for (int j = 0; j < 4; j++)
#pragma unroll
            for (int r = 0; r < 4; r++) acc[i][j][r] = 0.f;

    issue(0);
    asm volatile("cp.async.commit_group;\n");
    issue(1);
    asm volatile("cp.async.commit_group;\n");

    for (int kt = 0; kt < nk; kt++) {
        asm volatile("cp.async.wait_group %0;\n" :: "n"(1));
        __syncthreads();
        if (kt + 2 < nk) issue(kt + 2);
        asm volatile("cp.async.commit_group;\n");

        const int st = kt % STAGES;
        const uint32_t a_st = asm_u32 + (uint32_t)(st * A_ST_H * 2) + a_lane;
        const uint32_t b_st = bsm_u32 + (uint32_t)(st * B_ST_H * 2) + b_lane;
#pragma unroll
        for (int kk = 0; kk < 4; kk++) {
            uint32_t af[4][4];
#pragma unroll
            for (int im = 0; im < 4; im++)
                ldsm4(af[im][0], af[im][1], af[im][2], af[im][3],
                      a_st + (uint32_t)(((m_base + im * 16) * AS_H + kk * 16) * 2));
            uint32_t bf[2][4];
#pragma unroll
            for (int t = 0; t < 2; t++)
                ldsm4t(bf[t][0], bf[t][1], bf[t][2], bf[t][3],
                       b_st + (uint32_t)((kk * 16 * BS_H + n_base + t * 16) * 2));
#pragma unroll
            for (int im = 0; im < 4; im++)
#pragma unroll
                for (int in = 0; in < 4; in++)
                    mma_fp16(acc[im][in], af[im], &bf[in >> 1][(in & 1) * 2]);
        }
    }
    __syncthreads();   // mainloop smem dead; epilogue may reuse

    // -------- bias --------
    float b0[4], b1[4];
#pragma unroll
    for (int in = 0; in < 4; in++) {
        if (bias != nullptr) {
            const int c = tN + n_base + in * 8 + 2 * (lane & 3);
            b0[in] = __ldg(bias + c);
            b1[in] = __ldg(bias + c + 1);
        } else { b0[in] = 0.f; b1[in] = 0.f; }
    }
#pragma unroll
    for (int im = 0; im < 4; im++)
#pragma unroll
        for (int in = 0; in < 4; in++) {
            acc[im][in][0] += b0[in];
            acc[im][in][1] += b1[in];
            acc[im][in][2] += b0[in];
            acc[im][in][3] += b1[in];
        }

    if (FUSE_PV) {
        // ---- start ctx loads (overlap with softmax math) ----
        __half* Psm = (__half*)(smraw + P_OFF);
        __half* Csm = (__half*)(smraw + CTX_OFF);
        float* red = (float*)(smraw + RED_OFF);
        float* red2 = red + 512;
        const int bh = (tM >> 12) * HH + blockIdx.x;   // b = tM/T, h = blockIdx.x
        const __half* cg = ctxg + ((size_t)bh << 14);
#pragma unroll
        for (int j = 0; j < 8; j++) {                   // 128 rows x 128 halves
            const int ci = tid + 256 * j;
            const int r = ci >> 4, c = (ci & 15) * 8;
            cp16(Csm + r * BS_H + c, cg + (size_t)r * HD + c);
        }
        asm volatile("cp.async.commit_group;\n");

        // ---- row softmax over 128 cols (4 n-warp groups via smem) ----
        const int wn = warp >> 1;
        float m0[4], m1[4];
#pragma unroll
        for (int im = 0; im < 4; im++) {
            float a = -1e30f, b = -1e30f;
#pragma unroll
            for (int in = 0; in < 4; in++) {
                a = fmaxf(a, fmaxf(acc[im][in][0], acc[im][in][1]));
                b = fmaxf(b, fmaxf(acc[im][in][2], acc[im][in][3]));
            }
            a = fmaxf(a, __shfl_xor_sync(0xffffffffu, a, 1));
            a = fmaxf(a, __shfl_xor_sync(0xffffffffu, a, 2));
            b = fmaxf(b, __shfl_xor_sync(0xffffffffu, b, 1));
            b = fmaxf(b, __shfl_xor_sync(0xffffffffu, b, 2));
            m0[im] = a; m1[im] = b;
        }
        if ((lane & 3) == 0) {
#pragma unroll
            for (int im = 0; im < 4; im++) {
                const int r = m_base + im * 16 + (lane >> 2);
                red[r * 4 + wn] = m0[im];
                red[(r + 8) * 4 + wn] = m1[im];
            }
        }
        __syncthreads();
        float M0[4], M1[4];
#pragma unroll
        for (int im = 0; im < 4; im++) {
            const int r = m_base + im * 16 + (lane >> 2);
            M0[im] = fmaxf(fmaxf(red[r * 4], red[r * 4 + 1]),
                           fmaxf(red[r * 4 + 2], red[r * 4 + 3]));
            M1[im] = fmaxf(fmaxf(red[(r + 8) * 4], red[(r + 8) * 4 + 1]),
                           fmaxf(red[(r + 8) * 4 + 2], red[(r + 8) * 4 + 3]));
        }
        float s0[4], s1[4];
#pragma unroll
        for (int im = 0; im < 4; im++) {
            float sa = 0.f, sb = 0.f;
#pragma unroll
            for (int in = 0; in < 4; in++) {
                acc[im][in][0] = __expf(acc[im][in][0] - M0[im]);
                acc[im][in][1] = __expf(acc[im][in][1] - M0[im]);
                acc[im][in][2] = __expf(acc[im][in][2] - M1[im]);
                acc[im][in][3] = __expf(acc[im][in][3] - M1[im]);
                sa += acc[im][in][0] + acc[im][in][1];
                sb += acc[im][in][2] + acc[im][in][3];
            }
            sa += __shfl_xor_sync(0xffffffffu, sa, 1);
            sa += __shfl_xor_sync(0xffffffffu, sa, 2);
            sb += __shfl_xor_sync(0xffffffffu, sb, 1);
            sb += __shfl_xor_sync(0xffffffffu, sb, 2);
            s0[im] = sa; s1[im] = sb;
        }
        if ((lane & 3) == 0) {
#pragma unroll
            for (int im = 0; im < 4; im++) {
                const int r = m_base + im * 16 + (lane >> 2);
                red2[r * 4 + wn] = s0[im];
                red2[(r + 8) * 4 + wn] = s1[im];
            }
        }
        __syncthreads();
        // ---- P (fp16) to smem ----
#pragma unroll
        for (int im = 0; im < 4; im++) {
            const int r = m_base + im * 16 + (lane >> 2);
            const float inv0 = 1.f / (red2[r * 4] + red2[r * 4 + 1] +
                                      red2[r * 4 + 2] + red2[r * 4 + 3]);
            const float inv1 = 1.f / (red2[(r + 8) * 4] + red2[(r + 8) * 4 + 1] +
                                      red2[(r + 8) * 4 + 2] + red2[(r + 8) * 4 + 3]);
#pragma unroll
            for (int in = 0; in < 4; in++) {
                const int c = n_base + in * 8 + 2 * (lane & 3);
                *(half2*)(Psm + (size_t)r * BS_H + c) =
                    __floats2half2_rn(acc[im][in][0] * inv0, acc[im][in][1] * inv0);
                *(half2*)(Psm + (size_t)(r + 8) * BS_H + c) =
                    __floats2half2_rn(acc[im][in][2] * inv1, acc[im][in][3] * inv1);
            }
        }
        asm volatile("cp.async.wait_group 0;\n");
        __syncthreads();

        // ---- second GEMM: y[128,128] = P @ ctx ----
        float ac2[4][4][4];
#pragma unroll
        for (int i = 0; i < 4; i++)
#pragma unroll
            for (int j = 0; j < 4; j++)
#pragma unroll
                for (int r = 0; r < 4; r++) ac2[i][j][r] = 0.f;

        const uint32_t p_u32 = (uint32_t)__cvta_generic_to_shared(Psm) + b_lane;
        const uint32_t c_u32 = (uint32_t)__cvta_generic_to_shared(Csm) + b_lane;
#pragma unroll
        for (int kk = 0; kk < 8; kk++) {
            uint32_t af[4][4];
#pragma unroll
            for (int im = 0; im < 4; im++)
                ldsm4(af[im][0], af[im][1], af[im][2], af[im][3],
                      p_u32 + (uint32_t)(((m_base + im * 16) * BS_H + kk * 16) * 2));
            uint32_t bf[2][4];
#pragma unroll
            for (int t = 0; t < 2; t++)
                ldsm4t(bf[t][0], bf[t][1], bf[t][2], bf[t][3],
                       c_u32 + (uint32_t)((kk * 16 * BS_H + n_base + t * 16) * 2));
#pragma unroll
            for (int im = 0; im < 4; im++)
#pragma unroll
                for (int in = 0; in < 4; in++)
                    mma_fp16(ac2[im][in], af[im], &bf[in >> 1][(in & 1) * 2]);
        }
        // y write (f32) — tile cols = head blockIdx.x
#pragma unroll
        for (int im = 0; im < 4; im++) {
            const int r0 = tM + m_base + im * 16 + (lane >> 2);
#pragma unroll
            for (int in = 0; in < 4; in++) {
                const int c = tN + n_base + in * 8 + 2 * (lane & 3);
                *(float2*)((float*)C + (size_t)r0 * ldc + c) =
                    make_float2(ac2[im][in][0], ac2[im][in][1]);
                *(float2*)((float*)C + (size_t)(r0 + 8) * ldc + c) =
                    make_float2(ac2[im][in][2], ac2[im][in][3]);
            }
        }
    } else {
#pragma unroll
        for (int im = 0; im < 4; im++) {
            const int r0 = tM + m_base + im * 16 + (lane >> 2);
#pragma unroll
            for (int in = 0; in < 4; in++) {
                const int c = tN + n_base + in * 8 + 2 * (lane & 3);
                *(float2*)((float*)C + (size_t)r0 * ldc + c) =
                    make_float2(acc[im][in][0], acc[im][in][1]);
                *(float2*)((float*)C + (size_t)(r0 + 8) * ldc + c) =
                    make_float2(acc[im][in][2], acc[im][in][3]);
            }
        }
    }
}

// ---------------------------------------------------------------------------
// k column softmax stats — SINGLE PASS, rescaled partials.
// grid: B*32 (b, 32-col group), 512 threads = 32 cols x 16 row-chunks(32).
// Each thread: 32 values in regs -> local max + local expsum; block combine
// via rescaling: M = max m_p ; S = sum s_p * exp(m_p - M).
// ---------------------------------------------------------------------------
__global__ void __launch_bounds__(512)
kcol_stats(const float* __restrict__ k, float* __restrict__ om,
           float* __restrict__ os) {
    const int b = blockIdx.x >> 5;
    const int cg = blockIdx.x & 31;
    const int cl = threadIdx.x & 31;
    const int chunk = threadIdx.x >> 5;          // 0..15
    const int col = cg * 32 + cl;
    const float* p = k + (size_t)b * NN * DD + (size_t)(chunk * 32) * DD + col;

    float v[32];
    float m = -1e30f;
#pragma unroll
    for (int i = 0; i < 32; i++) {
        v[i] = p[(size_t)i * DD];
        m = fmaxf(m, v[i]);
    }
    float s = 0.f;
#pragma unroll
    for (int i = 0; i < 32; i++) s += __expf(v[i] - m);

    __shared__ float sm[16][32], ss[16][32];
    sm[chunk][cl] = m;
    ss[chunk][cl] = s;
    __syncthreads();
    if (chunk == 0) {
        float M = sm[0][cl];
#pragma unroll
        for (int i = 1; i < 16; i++) M = fmaxf(M, sm[i][cl]);
        float S = 0.f;
#pragma unroll
        for (int i = 0; i < 16; i++) S += ss[i][cl] * __expf(sm[i][cl] - M);
        om[b * DD + col] = M;
        os[b * DD + col] = S;
    }
}

// ---------------------------------------------------------------------------
// context partials: cp[split,bh,dk,dv] = (1/s_dk) * sum_n exp(k-m_dk) * v
// NSPLIT=8 splits of 64 rows each (2 c-iters of 32)
// ---------------------------------------------------------------------------
__global__ void __launch_bounds__(256)
context_part(const float* __restrict__ k, const float* __restrict__ v,
             const float* __restrict__ km, const float* __restrict__ ks,
             float* __restrict__ cp) {
    const int bh = blockIdx.x;
    const int b = bh >> 3, h = bh & 7;
    const int split = blockIdx.y;
    __shared__ float Ks[32][132], Vs[32][132];

    const float* kb = k + (size_t)b * NN * DD + h * HD;
    const float* vb = v + (size_t)b * NN * DD + h * HD;
    const float* kmb = km + b * DD + h * HD;
    const float* ksb = ks + b * DD + h * HD;

    float acc[8][8];
#pragma unroll
    for (int i = 0; i < 8; i++)
#pragma unroll
        for (int j = 0; j < 8; j++) acc[i][j] = 0.f;

    const int tx = threadIdx.x & 15, ty = threadIdx.x >> 4;

    for (int c = 0; c < 2; c++) {
        const int n0 = split * 64 + c * 32;
        for (int t = threadIdx.x; t < 32 * 128; t += 256) {
            int nn = t >> 7, dd = t & 127;
            Ks[nn][dd] = __expf(kb[(size_t)(n0 + nn) * DD + dd] - kmb[dd]);
            Vs[nn][dd] = vb[(size_t)(n0 + nn) * DD + dd];
        }
        __syncthreads();
#pragma unroll 8
        for (int nn = 0; nn < 32; nn++) {
            float kr[8], vr[8];
#pragma unroll
            for (int i = 0; i < 8; i++) kr[i] = Ks[nn][ty * 8 + i];
#pragma unroll
            for (int j = 0; j < 8; j++) vr[j] = Vs[nn][tx * 8 + j];
#pragma unroll
            for (int i = 0; i < 8; i++)
#pragma unroll
                for (int j = 0; j < 8; j++) acc[i][j] += kr[i] * vr[j];
        }
        __syncthreads();
    }

    float* out = cp + ((size_t)split * 32 + bh) * (HD * HD);
#pragma unroll
    for (int i = 0; i < 8; i++) {
        const int dk = ty * 8 + i;
        const float rs = 1.f / ksb[dk];
#pragma unroll
        for (int j = 0; j < 8; j++)
            out[(size_t)dk * HD + tx * 8 + j] = acc[i][j] * rs;
    }
}

// sum NSPLIT partials; fp16 output [bh][dk][dv] (B operand of fused PV)
__global__ void ctx_reduce(const float* __restrict__ cp, __half* __restrict__ ctx) {
    const size_t i = (size_t)blockIdx.x * 256 + threadIdx.x;
    float s = 0.f;
#pragma unroll
    for (int p = 0; p < NSPLIT; p++) s += cp[i + (size_t)p * 524288];
    ctx[i] = __float2half_rn(s);
}

// ---------------------------------------------------------------------------
// Launch
// ---------------------------------------------------------------------------
extern "C" void kernel_launch(void* const* d_in, const int* in_sizes, int n_in,
                              void* d_out, int out_size) {
    const float* x     = (const float*)d_in[0];
    const float* cond  = (const float*)d_in[1];
    const float* ln_g  = (const float*)d_in[2];
    const float* ln_b  = (const float*)d_in[3];
    const float* tln_g = (const float*)d_in[4];
    const float* tln_b = (const float*)d_in[5];
    const float* Wq    = (const float*)d_in[6];
    const float* bq    = (const float*)d_in[7];
    const float* Wk    = (const float*)d_in[8];
    const float* bk    = (const float*)d_in[9];
    const float* Wv    = (const float*)d_in[10];
    const float* bv    = (const float*)d_in[11];
    float* y = (float*)d_out;

    float* base = nullptr;
    cudaGetSymbolAddress((void**)&base, g_buf);
    __half* xn   = (__half*)(base + OFF_XN);
    __half* cn   = (__half*)(base + OFF_CN);
    float*  kk   = base + OFF_K;
    float*  vv   = base + OFF_V;
    float*  km   = base + OFF_KM;
    float*  ks   = base + OFF_KS;
    float*  cp   = base + OFF_CP;
    __half* ctx  = (__half*)(base + OFF_CTX);
    __half* wq16 = (__half*)(base + OFF_WQ16);
    __half* wk16 = (__half*)(base + OFF_WK16);
    __half* wv16 = (__half*)(base + OFF_WV16);

    cudaFuncSetAttribute(gemm_fp16<true, float>,
                         cudaFuncAttributeMaxDynamicSharedMemorySize, SMEM_BYTES);
    cudaFuncSetAttribute(gemm_fp16<false, float>,
                         cudaFuncAttributeMaxDynamicSharedMemorySize, SMEM_BYTES);

    // 0: convert weights to fp16; LN(cond)
    conv_weights<<<2560, 256>>>(Wq, Wk, Wv, wq16);
    ln_kernel<LL><<<BB * NN, 256>>>(cond, tln_g, tln_b, cn);

    // 1: k,v = cn @ W{k,v} + b fused in one launch (f32 outputs)
    gemm_fp16<false, float><<<dim3(2 * DD / 128, (BB * NN) / 128, 1), 256, SMEM_BYTES>>>(
        cn, wk16, bk, kk, wv16, bv, vv, nullptr,
        LL, LL, DD, DD);

    // 2: k column softmax stats (single pass, rescaled partials)
    kcol_stats<<<BB * 32, 512>>>(kk, km, ks);

    // 3-4: context = softmax_N(k)^T @ v  (8-way N split + fp16 reduce)
    context_part<<<dim3(BB * HH, NSPLIT), 256>>>(kk, vv, km, ks, cp);
    ctx_reduce<<<(BB * HH * HD * HD) / 256, 256>>>(cp, ctx);

    // 5: LN(x) (fp16 output) — just before the fused kernel
    ln_kernel<DD><<<BB * TT, 256>>>(x, ln_g, ln_b, xn);

    // 6: FUSED: q = softmax_head(xn @ Wq + bq); y = q @ ctx  -> d_out (f32)
    gemm_fp16<true, float><<<dim3(DD / 128, (BB * TT) / 128, 1), 256, SMEM_BYTES>>>(
        xn, wq16, bq, y, nullptr, nullptr, nullptr, ctx,
        DD, DD, DD, DD);
}

// round 12
// speedup vs baseline: 2.1859x; 1.1158x over previous
#include <cuda_runtime.h>
#include <cuda_fp16.h>
#include <cstdint>

// ---------------------------------------------------------------------------
// Problem constants (fixed shapes from reference setup_inputs)
// ---------------------------------------------------------------------------
#define BB   4
#define TT   4096
#define NN   512
#define DD   1024
#define LL   768
#define HH   8
#define HD   128

// ---------------------------------------------------------------------------
// Scratch (single __device__ array; offsets in floats)
// ---------------------------------------------------------------------------
#define NSPLIT 8
#define OFF_XN   0LL                                 // half [B*T,D]
#define OFF_CN   (OFF_XN + 8388608LL)                // half [B*N,L]
#define OFF_K    (OFF_CN + 786432LL)                 // f32  [B*N,D]
#define OFF_V    (OFF_K  + 2097152LL)                // f32  [B*N,D]
#define OFF_KM   (OFF_V  + 2097152LL)                // f32  [B,D]
#define OFF_KS   (OFF_KM + 4096LL)                   // f32  [B,D]
#define OFF_CP   (OFF_KS + 4096LL)                   // f32  [NSPLIT,B*H,128,128]
#define OFF_CTX  (OFF_CP + 4194304LL)                // half [B*H,dk,dv]
#define OFF_WQ16 (OFF_CTX + 262144LL)                // half [1024,1024]
#define OFF_WK16 (OFF_WQ16 + 524288LL)               // half [768,1024]
#define OFF_WV16 (OFF_WK16 + 393216LL)               // half [768,1024]
#define SCRATCH_TOTAL (OFF_WV16 + 393216LL)

__device__ __align__(256) float g_buf[SCRATCH_TOTAL];

// ---------------------------------------------------------------------------
// Helpers
// ---------------------------------------------------------------------------
__device__ __forceinline__ void mma_fp16(float* c, const uint32_t* a, const uint32_t* b) {
    asm volatile(
        "mma.sync.aligned.m16n8k16.row.col.f32.f16.f16.f32 "
        "{%0,%1,%2,%3}, {%4,%5,%6,%7}, {%8,%9}, {%0,%1,%2,%3};\n"
        : "+f"(c[0]), "+f"(c[1]), "+f"(c[2]), "+f"(c[3])
        : "r"(a[0]), "r"(a[1]), "r"(a[2]), "r"(a[3]),
          "r"(b[0]), "r"(b[1]));
}

__device__ __forceinline__ void ldsm4(uint32_t& r0, uint32_t& r1, uint32_t& r2,
                                      uint32_t& r3, uint32_t addr) {
    asm volatile("ldmatrix.sync.aligned.m8n8.x4.shared.b16 {%0,%1,%2,%3}, [%4];\n"
                 : "=r"(r0), "=r"(r1), "=r"(r2), "=r"(r3) : "r"(addr));
}

__device__ __forceinline__ void ldsm4t(uint32_t& r0, uint32_t& r1, uint32_t& r2,
                                       uint32_t& r3, uint32_t addr) {
    asm volatile("ldmatrix.sync.aligned.m8n8.x4.trans.shared.b16 {%0,%1,%2,%3}, [%4];\n"
                 : "=r"(r0), "=r"(r1), "=r"(r2), "=r"(r3) : "r"(addr));
}

__device__ __forceinline__ void cp16(void* s, const void* g) {
    uint32_t sa = (uint32_t)__cvta_generic_to_shared(s);
    asm volatile("cp.async.cg.shared.global [%0], [%1], 16;\n" :: "r"(sa), "l"(g));
}

// ---------------------------------------------------------------------------
// Convert weights f32 -> f16 (layout kept [K, N])
// ---------------------------------------------------------------------------
__global__ void conv_weights(const float* __restrict__ wq, const float* __restrict__ wk,
                             const float* __restrict__ wv, __half* __restrict__ out) {
    const size_t fi = ((size_t)blockIdx.x * 256 + threadIdx.x) * 4;
    const float* src;
    size_t off;
    if (fi < 1048576) { src = wq; off = fi; }
    else if (fi < 1048576 + 786432) { src = wk; off = fi - 1048576; }
    else { src = wv; off = fi - (1048576 + 786432); }
    float4 v = *(const float4*)(src + off);
    *(half2*)(out + fi) = __floats2half2_rn(v.x, v.y);
    *(half2*)(out + fi + 2) = __floats2half2_rn(v.z, v.w);
}

// ---------------------------------------------------------------------------
// LayerNorm D=1024, vectorized: 256 thr, one float4 per thread
// ---------------------------------------------------------------------------
__global__ void ln1024(const float* __restrict__ x, const float* __restrict__ g,
                       const float* __restrict__ bta, __half* __restrict__ out) {
    const size_t row = blockIdx.x;
    const int c = threadIdx.x * 4;
    const float4 v = *(const float4*)(x + row * DD + c);
    float s = v.x + v.y + v.z + v.w;
    float sq = v.x * v.x + v.y * v.y + v.z * v.z + v.w * v.w;
#pragma unroll
    for (int o = 16; o; o >>= 1) {
        s += __shfl_xor_sync(0xffffffffu, s, o);
        sq += __shfl_xor_sync(0xffffffffu, sq, o);
    }
    __shared__ float sm[8], sv[8];
    const int w = threadIdx.x >> 5;
    if ((threadIdx.x & 31) == 0) { sm[w] = s; sv[w] = sq; }
    __syncthreads();
    if (threadIdx.x < 32) {
        s = (threadIdx.x < 8) ? sm[threadIdx.x] : 0.f;
        sq = (threadIdx.x < 8) ? sv[threadIdx.x] : 0.f;
#pragma unroll
        for (int o = 4; o; o >>= 1) {
            s += __shfl_xor_sync(0xffffffffu, s, o);
            sq += __shfl_xor_sync(0xffffffffu, sq, o);
        }
        if (threadIdx.x == 0) { sm[0] = s; sv[0] = sq; }
    }
    __syncthreads();
    const float mean = sm[0] * (1.f / DD);
    const float rstd = rsqrtf(sv[0] * (1.f / DD) - mean * mean + 1e-5f);
    const float4 g4 = *(const float4*)(g + c);
    const float4 b4 = *(const float4*)(bta + c);
    half2 h0 = __floats2half2_rn((v.x - mean) * rstd * g4.x + b4.x,
                                 (v.y - mean) * rstd * g4.y + b4.y);
    half2 h1 = __floats2half2_rn((v.z - mean) * rstd * g4.z + b4.z,
                                 (v.w - mean) * rstd * g4.w + b4.w);
    *(half2*)(out + row * DD + c) = h0;
    *(half2*)(out + row * DD + c + 2) = h1;
}

// ---------------------------------------------------------------------------
// LayerNorm generic (used for L=768 cond path)
// ---------------------------------------------------------------------------
template <int DIM>
__global__ void ln_kernel(const float* __restrict__ x, const float* __restrict__ g,
                          const float* __restrict__ bta, __half* __restrict__ out) {
    constexpr int PER = DIM / 256;
    const size_t row = blockIdx.x;
    const float* xr = x + row * DIM;
    float v[PER];
    float s = 0.f, sq = 0.f;
#pragma unroll
    for (int i = 0; i < PER; i++) {
        v[i] = xr[threadIdx.x + 256 * i];
        s += v[i];
        sq += v[i] * v[i];
    }
#pragma unroll
    for (int o = 16; o; o >>= 1) {
        s += __shfl_xor_sync(0xffffffffu, s, o);
        sq += __shfl_xor_sync(0xffffffffu, sq, o);
    }
    __shared__ float sm[8], sv[8];
    int w = threadIdx.x >> 5;
    if ((threadIdx.x & 31) == 0) { sm[w] = s; sv[w] = sq; }
    __syncthreads();
    if (threadIdx.x < 32) {
        s = (threadIdx.x < 8) ? sm[threadIdx.x] : 0.f;
        sq = (threadIdx.x < 8) ? sv[threadIdx.x] : 0.f;
#pragma unroll
        for (int o = 4; o; o >>= 1) {
            s += __shfl_xor_sync(0xffffffffu, s, o);
            sq += __shfl_xor_sync(0xffffffffu, sq, o);
        }
        if (threadIdx.x == 0) { sm[0] = s; sv[0] = sq; }
    }
    __syncthreads();
    const float mean = sm[0] * (1.f / DIM);
    const float var = sv[0] * (1.f / DIM) - mean * mean;
    const float rstd = rsqrtf(var + 1e-5f);
    __half* orow = out + row * DIM;
#pragma unroll
    for (int i = 0; i < PER; i++) {
        int c = threadIdx.x + 256 * i;
        orow[c] = __float2half_rn((v[i] - mean) * rstd * g[c] + bta[c]);
    }
}

// ---------------------------------------------------------------------------
// fp16 tensor-core GEMM: 128x128 tile, BK=64, cp.async 3-stage, f32 accum.
// 8 warps (2m x 4n), warp tile 64x32.
// FUSE_PV: tile == one (b,head): row softmax -> P(fp16, smem) -> P @ ctx
//          (ctx cp.async'd during softmax) -> y (f32) written directly.
// Dual (Bm2!=null): grid.x split between {Bm,bias,C} and {Bm2,bias2,C2}.
// ---------------------------------------------------------------------------
#define STAGES 3
#define AS_H 72              // halves per A smem row (64 + 8 pad)
#define BS_H 136             // halves per B smem row (128 + 8 pad)
#define A_ST_H (128 * AS_H)
#define B_ST_H (64 * BS_H)
#define SMEM_BYTES (STAGES * (A_ST_H + B_ST_H) * 2)   // 107520
// FUSE epilogue smem plan (inside the 107520 bytes, reused post-mainloop):
#define P_OFF   8192
#define CTX_OFF (P_OFF + 128 * BS_H * 2)              // 43008
#define RED_OFF (CTX_OFF + 128 * BS_H * 2)            // 77824 (+4KB <= 107520)

template <bool FUSE_PV, typename OutT>
__global__ void __launch_bounds__(256, 2)
gemm_fp16(const __half* __restrict__ A, const __half* __restrict__ Bm,
          const float* __restrict__ bias, OutT* __restrict__ C,
          const __half* __restrict__ Bm2, const float* __restrict__ bias2,
          OutT* __restrict__ C2, const __half* __restrict__ ctxg,
          int K, int lda, int ldb, int ldc) {
    extern __shared__ __align__(16) char smraw[];
    __half* Asm = (__half*)smraw;
    __half* Bsm = Asm + STAGES * A_ST_H;

    int tN;
    if (Bm2 != nullptr) {
        const int half_g = gridDim.x >> 1;
        if (blockIdx.x >= half_g) {
            Bm = Bm2; bias = bias2; C = C2;
            tN = (blockIdx.x - half_g) * 128;
        } else {
            tN = blockIdx.x * 128;
        }
    } else {
        tN = blockIdx.x * 128;
    }
    const int tM = blockIdx.y * 128;
    const int tid = threadIdx.x;
    const int lane = tid & 31, warp = tid >> 5;
    const int m_base = (warp & 1) * 64;
    const int n_base = (warp >> 1) * 32;

    const __half* Ag = A + (size_t)tM * lda;
    const __half* Bg = Bm + tN;
    const int nk = K >> 6;   // BK = 64

    auto issue = [&](int kt) {
        const int st = kt % STAGES;
        __half* Al = Asm + st * A_ST_H;
        __half* Bl = Bsm + st * B_ST_H;
        const int k0 = kt << 6;
#pragma unroll
        for (int j = 0; j < 4; j++) {
            const int ci = tid + 256 * j;
            const int r = ci >> 3, c = (ci & 7) * 8;
            cp16(Al + r * AS_H + c, Ag + (size_t)r * lda + k0 + c);
        }
#pragma unroll
        for (int j = 0; j < 4; j++) {
            const int ci = tid + 256 * j;
            const int r = ci >> 4, c = (ci & 15) * 8;
            cp16(Bl + r * BS_H + c, Bg + (size_t)(k0 + r) * ldb + c);
        }
    };

    const uint32_t asm_u32 = (uint32_t)__cvta_generic_to_shared(Asm);
    const uint32_t bsm_u32 = (uint32_t)__cvta_generic_to_shared(Bsm);
    const uint32_t a_lane = (uint32_t)(((lane & 15) * AS_H + (lane >> 4) * 8) * 2);
    const uint32_t b_lane = (uint32_t)(((lane & 15) * BS_H + (lane >> 4) * 8) * 2);

    float acc[4][4][4];
#pragma unroll
    for (int i = 0; i < 4; i++)
#pragma unroll
        for (int j = 0; j < 4; j++)
#pragma unroll
            for (int r = 0; r < 4; r++) acc[i][j][r] = 0.f;

    issue(0);
    asm volatile("cp.async.commit_group;\n");
    issue(1);
    asm volatile("cp.async.commit_group;\n");

    for (int kt = 0; kt < nk; kt++) {
        asm volatile("cp.async.wait_group %0;\n" :: "n"(1));
        __syncthreads();
        if (kt + 2 < nk) issue(kt + 2);
        asm volatile("cp.async.commit_group;\n");

        const int st = kt % STAGES;
        const uint32_t a_st = asm_u32 + (uint32_t)(st * A_ST_H * 2) + a_lane;
        const uint32_t b_st = bsm_u32 + (uint32_t)(st * B_ST_H * 2) + b_lane;
#pragma unroll
        for (int kk = 0; kk < 4; kk++) {
            uint32_t af[4][4];
#pragma unroll
            for (int im = 0; im < 4; im++)
                ldsm4(af[im][0], af[im][1], af[im][2], af[im][3],
                      a_st + (uint32_t)(((m_base + im * 16) * AS_H + kk * 16) * 2));
            uint32_t bf[2][4];
#pragma unroll
            for (int t = 0; t < 2; t++)
                ldsm4t(bf[t][0], bf[t][1], bf[t][2], bf[t][3],
                       b_st + (uint32_t)((kk * 16 * BS_H + n_base + t * 16) * 2));
#pragma unroll
            for (int im = 0; im < 4; im++)
#pragma unroll
                for (int in = 0; in < 4; in++)
                    mma_fp16(acc[im][in], af[im], &bf[in >> 1][(in & 1) * 2]);
        }
    }
    __syncthreads();   // mainloop smem dead; epilogue may reuse

    // -------- bias --------
    float b0[4], b1[4];
#pragma unroll
    for (int in = 0; in < 4; in++) {
        if (bias != nullptr) {
            const int c = tN + n_base + in * 8 + 2 * (lane & 3);
            b0[in] = __ldg(bias + c);
            b1[in] = __ldg(bias + c + 1);
        } else { b0[in] = 0.f; b1[in] = 0.f; }
    }
#pragma unroll
    for (int im = 0; im < 4; im++)
#pragma unroll
        for (int in = 0; in < 4; in++) {
            acc[im][in][0] += b0[in];
            acc[im][in][1] += b1[in];
            acc[im][in][2] += b0[in];
            acc[im][in][3] += b1[in];
        }

    if (FUSE_PV) {
        // ---- start ctx loads (overlap with softmax math) ----
        __half* Psm = (__half*)(smraw + P_OFF);
        __half* Csm = (__half*)(smraw + CTX_OFF);
        float* red = (float*)(smraw + RED_OFF);
        float* red2 = red + 512;
        const int bh = (tM >> 12) * HH + blockIdx.x;   // b = tM/T, h = blockIdx.x
        const __half* cg = ctxg + ((size_t)bh << 14);
#pragma unroll
        for (int j = 0; j < 8; j++) {                   // 128 rows x 128 halves
            const int ci = tid + 256 * j;
            const int r = ci >> 4, c = (ci & 15) * 8;
            cp16(Csm + r * BS_H + c, cg + (size_t)r * HD + c);
        }
        asm volatile("cp.async.commit_group;\n");

        // ---- row softmax over 128 cols (4 n-warp groups via smem) ----
        const int wn = warp >> 1;
        float m0[4], m1[4];
#pragma unroll
        for (int im = 0; im < 4; im++) {
            float a = -1e30f, b = -1e30f;
#pragma unroll
            for (int in = 0; in < 4; in++) {
                a = fmaxf(a, fmaxf(acc[im][in][0], acc[im][in][1]));
                b = fmaxf(b, fmaxf(acc[im][in][2], acc[im][in][3]));
            }
            a = fmaxf(a, __shfl_xor_sync(0xffffffffu, a, 1));
            a = fmaxf(a, __shfl_xor_sync(0xffffffffu, a, 2));
            b = fmaxf(b, __shfl_xor_sync(0xffffffffu, b, 1));
            b = fmaxf(b, __shfl_xor_sync(0xffffffffu, b, 2));
            m0[im] = a; m1[im] = b;
        }
        if ((lane & 3) == 0) {
#pragma unroll
            for (int im = 0; im < 4; im++) {
                const int r = m_base + im * 16 + (lane >> 2);
                red[r * 4 + wn] = m0[im];
                red[(r + 8) * 4 + wn] = m1[im];
            }
        }
        __syncthreads();
        float M0[4], M1[4];
#pragma unroll
        for (int im = 0; im < 4; im++) {
            const int r = m_base + im * 16 + (lane >> 2);
            M0[im] = fmaxf(fmaxf(red[r * 4], red[r * 4 + 1]),
                           fmaxf(red[r * 4 + 2], red[r * 4 + 3]));
            M1[im] = fmaxf(fmaxf(red[(r + 8) * 4], red[(r + 8) * 4 + 1]),
                           fmaxf(red[(r + 8) * 4 + 2], red[(r + 8) * 4 + 3]));
        }
        float s0[4], s1[4];
#pragma unroll
        for (int im = 0; im < 4; im++) {
            float sa = 0.f, sb = 0.f;
#pragma unroll
            for (int in = 0; in < 4; in++) {
                acc[im][in][0] = __expf(acc[im][in][0] - M0[im]);
                acc[im][in][1] = __expf(acc[im][in][1] - M0[im]);
                acc[im][in][2] = __expf(acc[im][in][2] - M1[im]);
                acc[im][in][3] = __expf(acc[im][in][3] - M1[im]);
                sa += acc[im][in][0] + acc[im][in][1];
                sb += acc[im][in][2] + acc[im][in][3];
            }
            sa += __shfl_xor_sync(0xffffffffu, sa, 1);
            sa += __shfl_xor_sync(0xffffffffu, sa, 2);
            sb += __shfl_xor_sync(0xffffffffu, sb, 1);
            sb += __shfl_xor_sync(0xffffffffu, sb, 2);
            s0[im] = sa; s1[im] = sb;
        }
        if ((lane & 3) == 0) {
#pragma unroll
            for (int im = 0; im < 4; im++) {
                const int r = m_base + im * 16 + (lane >> 2);
                red2[r * 4 + wn] = s0[im];
                red2[(r + 8) * 4 + wn] = s1[im];
            }
        }
        __syncthreads();
        // ---- P (fp16) to smem ----
#pragma unroll
        for (int im = 0; im < 4; im++) {
            const int r = m_base + im * 16 + (lane >> 2);
            const float inv0 = 1.f / (red2[r * 4] + red2[r * 4 + 1] +
                                      red2[r * 4 + 2] + red2[r * 4 + 3]);
            const float inv1 = 1.f / (red2[(r + 8) * 4] + red2[(r + 8) * 4 + 1] +
                                      red2[(r + 8) * 4 + 2] + red2[(r + 8) * 4 + 3]);
#pragma unroll
            for (int in = 0; in < 4; in++) {
                const int c = n_base + in * 8 + 2 * (lane & 3);
                *(half2*)(Psm + (size_t)r * BS_H + c) =
                    __floats2half2_rn(acc[im][in][0] * inv0, acc[im][in][1] * inv0);
                *(half2*)(Psm + (size_t)(r + 8) * BS_H + c) =
                    __floats2half2_rn(acc[im][in][2] * inv1, acc[im][in][3] * inv1);
            }
        }
        asm volatile("cp.async.wait_group 0;\n");
        __syncthreads();

        // ---- second GEMM: y[128,128] = P @ ctx ----
        float ac2[4][4][4];
#pragma unroll
        for (int i = 0; i < 4; i++)
#pragma unroll
            for (int j = 0; j < 4; j++)
#pragma unroll
                for (int r = 0; r < 4; r++) ac2[i][j][r] = 0.f;

        const uint32_t p_u32 = (uint32_t)__cvta_generic_to_shared(Psm) + b_lane;
        const uint32_t c_u32 = (uint32_t)__cvta_generic_to_shared(Csm) + b_lane;
#pragma unroll
        for (int kk = 0; kk < 8; kk++) {
            uint32_t af[4][4];
#pragma unroll
            for (int im = 0; im < 4; im++)
                ldsm4(af[im][0], af[im][1], af[im][2], af[im][3],
                      p_u32 + (uint32_t)(((m_base + im * 16) * BS_H + kk * 16) * 2));
            uint32_t bf[2][4];
#pragma unroll
            for (int t = 0; t < 2; t++)
                ldsm4t(bf[t][0], bf[t][1], bf[t][2], bf[t][3],
                       c_u32 + (uint32_t)((kk * 16 * BS_H + n_base + t * 16) * 2));
#pragma unroll
            for (int im = 0; im < 4; im++)
#pragma unroll
                for (int in = 0; in < 4; in++)
                    mma_fp16(ac2[im][in], af[im], &bf[in >> 1][(in & 1) * 2]);
        }
        // y write (f32) — tile cols = head blockIdx.x
#pragma unroll
        for (int im = 0; im < 4; im++) {
            const int r0 = tM + m_base + im * 16 + (lane >> 2);
#pragma unroll
            for (int in = 0; in < 4; in++) {
                const int c = tN + n_base + in * 8 + 2 * (lane & 3);
                *(float2*)((float*)C + (size_t)r0 * ldc + c) =
                    make_float2(ac2[im][in][0], ac2[im][in][1]);
                *(float2*)((float*)C + (size_t)(r0 + 8) * ldc + c) =
                    make_float2(ac2[im][in][2], ac2[im][in][3]);
            }
        }
    } else {
#pragma unroll
        for (int im = 0; im < 4; im++) {
            const int r0 = tM + m_base + im * 16 + (lane >> 2);
#pragma unroll
            for (int in = 0; in < 4; in++) {
                const int c = tN + n_base + in * 8 + 2 * (lane & 3);
                *(float2*)((float*)C + (size_t)r0 * ldc + c) =
                    make_float2(acc[im][in][0], acc[im][in][1]);
                *(float2*)((float*)C + (size_t)(r0 + 8) * ldc + c) =
                    make_float2(acc[im][in][2], acc[im][in][3]);
            }
        }
    }
}

// ---------------------------------------------------------------------------
// k column softmax stats — single pass, rescaled partials.
// ---------------------------------------------------------------------------
__global__ void __launch_bounds__(512)
kcol_stats(const float* __restrict__ k, float* __restrict__ om,
           float* __restrict__ os) {
    const int b = blockIdx.x >> 5;
    const int cg = blockIdx.x & 31;
    const int cl = threadIdx.x & 31;
    const int chunk = threadIdx.x >> 5;          // 0..15
    const int col = cg * 32 + cl;
    const float* p = k + (size_t)b * NN * DD + (size_t)(chunk * 32) * DD + col;

    float v[32];
    float m = -1e30f;
#pragma unroll
    for (int i = 0; i < 32; i++) {
        v[i] = p[(size_t)i * DD];
        m = fmaxf(m, v[i]);
    }
    float s = 0.f;
#pragma unroll
    for (int i = 0; i < 32; i++) s += __expf(v[i] - m);

    __shared__ float sm[16][32], ss[16][32];
    sm[chunk][cl] = m;
    ss[chunk][cl] = s;
    __syncthreads();
    if (chunk == 0) {
        float M = sm[0][cl];
#pragma unroll
        for (int i = 1; i < 16; i++) M = fmaxf(M, sm[i][cl]);
        float S = 0.f;
#pragma unroll
        for (int i = 0; i < 16; i++) S += ss[i][cl] * __expf(sm[i][cl] - M);
        om[b * DD + col] = M;
        os[b * DD + col] = S;
    }
}

// ---------------------------------------------------------------------------
// context partials via fp16 MMA:
//   cp[split,bh,dk,dv] = (1/s_dk) * sum_{n in split} exp(k[n,dk]-m_dk) * v[n,dv]
// One CTA per (bh, split of 64 tokens). expk/v converted to fp16 in smem;
// A = expk^T via ldmatrix.x4.trans over [tok][dk] (reg order {r0,r2,r1,r3}).
// 8 warps, 2m x 4n, warp tile 64x32, 4 k-steps of 16 tokens.
// ---------------------------------------------------------------------------
__global__ void __launch_bounds__(256)
context_mma(const float* __restrict__ k, const float* __restrict__ v,
            const float* __restrict__ km, const float* __restrict__ ks,
            float* __restrict__ cp) {
    const int bh = blockIdx.x;
    const int b = bh >> 3, h = bh & 7;
    const int n0 = blockIdx.y * 64;
    __shared__ __half Ek[64 * BS_H], Vs[64 * BS_H];

    const float* kb = k + (size_t)b * NN * DD + h * HD;
    const float* vb = v + (size_t)b * NN * DD + h * HD;
    const float* kmb = km + b * DD + h * HD;
    const float* ksb = ks + b * DD + h * HD;

    const int tid = threadIdx.x;
    const int lane = tid & 31, warp = tid >> 5;
    const int m_base = (warp & 1) * 64;
    const int n_base = (warp >> 1) * 32;

    for (int t = tid; t < 64 * 128; t += 256) {
        const int r = t >> 7, c = t & 127;
        Ek[r * BS_H + c] = __float2half_rn(
            __expf(kb[(size_t)(n0 + r) * DD + c] - kmb[c]));
        Vs[r * BS_H + c] = __float2half_rn(vb[(size_t)(n0 + r) * DD + c]);
    }
    __syncthreads();

    float acc[4][4][4];
#pragma unroll
    for (int i = 0; i < 4; i++)
#pragma unroll
        for (int j = 0; j < 4; j++)
#pragma unroll
            for (int r = 0; r < 4; r++) acc[i][j][r] = 0.f;

    const uint32_t lane_off = (uint32_t)(((lane & 15) * BS_H + (lane >> 4) * 8) * 2);
    const uint32_t e_u32 = (uint32_t)__cvta_generic_to_shared(Ek) + lane_off;
    const uint32_t v_u32 = (uint32_t)__cvta_generic_to_shared(Vs) + lane_off;
#pragma unroll
    for (int kk = 0; kk < 4; kk++) {
        uint32_t af[4][4];
#pragma unroll
        for (int im = 0; im < 4; im++) {
            uint32_t r0, r1, r2, r3;
            ldsm4t(r0, r1, r2, r3,
                   e_u32 + (uint32_t)((kk * 16 * BS_H + m_base + im * 16) * 2));
            af[im][0] = r0; af[im][1] = r2; af[im][2] = r1; af[im][3] = r3;
        }
        uint32_t bf[2][4];
#pragma unroll
        for (int t = 0; t < 2; t++)
            ldsm4t(bf[t][0], bf[t][1], bf[t][2], bf[t][3],
                   v_u32 + (uint32_t)((kk * 16 * BS_H + n_base + t * 16) * 2));
#pragma unroll
        for (int im = 0; im < 4; im++)
#pragma unroll
            for (int in = 0; in < 4; in++)
                mma_fp16(acc[im][in], af[im], &bf[in >> 1][(in & 1) * 2]);
    }

    float* out = cp + ((size_t)blockIdx.y * 32 + bh) * (HD * HD);
#pragma unroll
    for (int im = 0; im < 4; im++) {
        const int r = m_base + im * 16 + (lane >> 2);
        const float rs0 = 1.f / ksb[r];
        const float rs1 = 1.f / ksb[r + 8];
#pragma unroll
        for (int in = 0; in < 4; in++) {
            const int c = n_base + in * 8 + 2 * (lane & 3);
            *(float2*)(out + (size_t)r * HD + c) =
                make_float2(acc[im][in][0] * rs0, acc[im][in][1] * rs0);
            *(float2*)(out + (size_t)(r + 8) * HD + c) =
                make_float2(acc[im][in][2] * rs1, acc[im][in][3] * rs1);
        }
    }
}

// sum NSPLIT partials; fp16 output [bh][dk][dv] (B operand of fused PV)
__global__ void ctx_reduce(const float* __restrict__ cp, __half* __restrict__ ctx) {
    const size_t i = (size_t)blockIdx.x * 256 + threadIdx.x;
    float s = 0.f;
#pragma unroll
    for (int p = 0; p < NSPLIT; p++) s += cp[i + (size_t)p * 524288];
    ctx[i] = __float2half_rn(s);
}

// ---------------------------------------------------------------------------
// Launch
// ---------------------------------------------------------------------------
extern "C" void kernel_launch(void* const* d_in, const int* in_sizes, int n_in,
                              void* d_out, int out_size) {
    const float* x     = (const float*)d_in[0];
    const float* cond  = (const float*)d_in[1];
    const float* ln_g  = (const float*)d_in[2];
    const float* ln_b  = (const float*)d_in[3];
    const float* tln_g = (const float*)d_in[4];
    const float* tln_b = (const float*)d_in[5];
    const float* Wq    = (const float*)d_in[6];
    const float* bq    = (const float*)d_in[7];
    const float* Wk    = (const float*)d_in[8];
    const float* bk    = (const float*)d_in[9];
    const float* Wv    = (const float*)d_in[10];
    const float* bv    = (const float*)d_in[11];
    float* y = (float*)d_out;

    float* base = nullptr;
    cudaGetSymbolAddress((void**)&base, g_buf);
    __half* xn   = (__half*)(base + OFF_XN);
    __half* cn   = (__half*)(base + OFF_CN);
    float*  kk   = base + OFF_K;
    float*  vv   = base + OFF_V;
    float*  km   = base + OFF_KM;
    float*  ks   = base + OFF_KS;
    float*  cp   = base + OFF_CP;
    __half* ctx  = (__half*)(base + OFF_CTX);
    __half* wq16 = (__half*)(base + OFF_WQ16);
    __half* wk16 = (__half*)(base + OFF_WK16);
    __half* wv16 = (__half*)(base + OFF_WV16);

    cudaFuncSetAttribute(gemm_fp16<true, float>,
                         cudaFuncAttributeMaxDynamicSharedMemorySize, SMEM_BYTES);
    cudaFuncSetAttribute(gemm_fp16<false, float>,
                         cudaFuncAttributeMaxDynamicSharedMemorySize, SMEM_BYTES);

    // 0: convert weights to fp16; LN(cond)
    conv_weights<<<2560, 256>>>(Wq, Wk, Wv, wq16);
    ln_kernel<LL><<<BB * NN, 256>>>(cond, tln_g, tln_b, cn);

    // 1: k,v = cn @ W{k,v} + b fused in one launch (f32 outputs)
    gemm_fp16<false, float><<<dim3(2 * DD / 128, (BB * NN) / 128, 1), 256, SMEM_BYTES>>>(
        cn, wk16, bk, kk, wv16, bv, vv, nullptr,
        LL, LL, DD, DD);

    // 2: k column softmax stats (single pass, rescaled partials)
    kcol_stats<<<BB * 32, 512>>>(kk, km, ks);

    // 3-4: context = softmax_N(k)^T @ v  (8-way split, fp16 MMA + reduce)
    context_mma<<<dim3(BB * HH, NSPLIT), 256>>>(kk, vv, km, ks, cp);
    ctx_reduce<<<(BB * HH * HD * HD) / 256, 256>>>(cp, ctx);

    // 5: LN(x) (vectorized, fp16 output)
    ln1024<<<BB * TT, 256>>>(x, ln_g, ln_b, xn);

    // 6: FUSED: q = softmax_head(xn @ Wq + bq); y = q @ ctx  -> d_out (f32)
    gemm_fp16<true, float><<<dim3(DD / 128, (BB * TT) / 128, 1), 256, SMEM_BYTES>>>(
        xn, wq16, bq, y, nullptr, nullptr, nullptr, ctx,
        DD, DD, DD, DD);
}